// round 1
// baseline (speedup 1.0000x reference)
#include <cuda_runtime.h>
#include <cstdint>

#define NN 50000
#define DD 128
#define RR 8
#define EE 800000
#define EDD 32
#define NR (NN*RR)      /* 400000 */
#define M2 (RR*NN)      /* 400000 */

// ---------------- scratch (static __device__, no allocation) ----------------
__device__ float g_deg[NR];
__device__ float g_aggx[NR*DD];          // [N*R, 128], index nor = n*R+r  (layer1 x-agg)
__device__ float g_aggef[NR*EDD];        // [N*R, 32]  shared by both layers
__device__ float g_aggh[M2*DD];          // [R*N, 128], index r*N+n       (layer2 h-agg)
__device__ float g_hpre[NN*DD];
__device__ float g_h[NN*DD];
__device__ float g_hs[NN*DD];            // h @ l2_Wself + (l2_bself + l2_blin)
__device__ float g_WeWlin1[RR*EDD*DD];   // [r*32+i][128]
__device__ float g_WeWlin2[EDD*DD];
__device__ float g_beWlin1[RR*DD];
__device__ float g_beWlin2[DD];
__device__ float g_bias1[DD];            // l1_blin + l1_bself
__device__ float g_bias2[DD];            // l2_blin + l2_bself
__device__ double g_s1a[DD], g_s2a[DD], g_s1b[DD], g_s2b[DD];
__device__ float g_sc1[DD], g_sh1[DD], g_sc2[DD], g_sh2[DD];

// ---------------- zero kernels ----------------
__global__ void zero_big_k() {
    size_t i = (size_t)blockIdx.x * blockDim.x + threadIdx.x;
    size_t stride = (size_t)gridDim.x * blockDim.x;
    float4 z = make_float4(0.f, 0.f, 0.f, 0.f);
    float4* a = (float4*)g_aggx;
    float4* h = (float4*)g_aggh;
    for (size_t j = i; j < (size_t)NR * DD / 4; j += stride) { a[j] = z; h[j] = z; }
    float4* e = (float4*)g_aggef;
    for (size_t j = i; j < (size_t)NR * EDD / 4; j += stride) e[j] = z;
    float4* d = (float4*)g_deg;
    for (size_t j = i; j < (size_t)NR / 4; j += stride) d[j] = z;
}

__global__ void zero_stats_k() {
    int d = threadIdx.x;
    g_s1a[d] = 0.0; g_s2a[d] = 0.0; g_s1b[d] = 0.0; g_s2b[d] = 0.0;
}

// ---------------- prep: fold We@Wlin, be@Wlin, biases ----------------
__global__ __launch_bounds__(128) void prep_k(
    const float* __restrict__ l1_We, const float* __restrict__ l1_Wlin,
    const float* __restrict__ l1_be, const float* __restrict__ l1_blin,
    const float* __restrict__ l1_bself,
    const float* __restrict__ l2_We, const float* __restrict__ l2_Wlin,
    const float* __restrict__ l2_be, const float* __restrict__ l2_blin,
    const float* __restrict__ l2_bself)
{
    __shared__ float sWe[EDD * DD];   // 16 KB
    __shared__ float sbe[DD];
    int r = blockIdx.x;
    int d = threadIdx.x;
    const float* We = (r < RR) ? l1_We : l2_We;
    const float* Wl = (r < RR) ? l1_Wlin : l2_Wlin;
    const float* be = (r < RR) ? l1_be : l2_be;
    for (int i = d; i < EDD * DD; i += 128) sWe[i] = We[i];
    sbe[d] = be[d];
    __syncthreads();

    float acc[EDD];
#pragma unroll
    for (int i = 0; i < EDD; i++) acc[i] = 0.f;
    float accb = 0.f;
    int rowoff = (r < RR) ? r * DD : 0;
    for (int k = 0; k < DD; k++) {
        float wl = Wl[(size_t)(rowoff + k) * DD + d];
        accb += sbe[k] * wl;
#pragma unroll
        for (int i = 0; i < EDD; i++) acc[i] += sWe[i * DD + k] * wl;
    }
    if (r < RR) {
#pragma unroll
        for (int i = 0; i < EDD; i++) g_WeWlin1[(size_t)(r * EDD + i) * DD + d] = acc[i];
        g_beWlin1[r * DD + d] = accb;
    } else {
#pragma unroll
        for (int i = 0; i < EDD; i++) g_WeWlin2[(size_t)i * DD + d] = acc[i];
        g_beWlin2[d] = accb;
        g_bias1[d] = l1_blin[d] + l1_bself[d];
        g_bias2[d] = l2_blin[d] + l2_bself[d];
    }
}

// ---------------- degree ----------------
__global__ void deg_k(const int* __restrict__ nout, const int* __restrict__ rel,
                      const float* __restrict__ w) {
    int e = blockIdx.x * blockDim.x + threadIdx.x;
    if (e < EE) atomicAdd(&g_deg[nout[e] * RR + rel[e]], w[e]);
}

// ---------------- scatter layer 1: aggx (+aggef, shared) ----------------
__global__ __launch_bounds__(256) void scatter1_k(
    const float* __restrict__ x, const int* __restrict__ nin,
    const int* __restrict__ nout, const int* __restrict__ rel,
    const float* __restrict__ w, const float* __restrict__ ef)
{
    int idx = blockIdx.x * 256 + threadIdx.x;
    int e = idx >> 5;
    int lane = idx & 31;
    if (e >= EE) return;
    int ni = __ldg(nin + e);
    int nor = __ldg(nout + e) * RR + __ldg(rel + e);
    float ew = __ldg(w + e) / g_deg[nor];

    float4 xv = ((const float4*)x)[(size_t)ni * 32 + lane];
    float* dst = &g_aggx[(size_t)nor * DD + lane * 4];
    atomicAdd(dst + 0, xv.x * ew);
    atomicAdd(dst + 1, xv.y * ew);
    atomicAdd(dst + 2, xv.z * ew);
    atomicAdd(dst + 3, xv.w * ew);

    float ev = ef[(size_t)e * EDD + lane] * ew;
    atomicAdd(&g_aggef[(size_t)nor * EDD + lane], ev);
}

// ---------------- scatter layer 2: aggh into transposed [R,N,128] ----------------
__global__ __launch_bounds__(256) void scatter2_k(
    const int* __restrict__ nin, const int* __restrict__ nout,
    const int* __restrict__ rel, const float* __restrict__ w)
{
    int idx = blockIdx.x * 256 + threadIdx.x;
    int e = idx >> 5;
    int lane = idx & 31;
    if (e >= EE) return;
    int ni = __ldg(nin + e);
    int no = __ldg(nout + e);
    int r  = __ldg(rel + e);
    int nor = no * RR + r;
    float ew = __ldg(w + e) / g_deg[nor];

    float4 hv = ((const float4*)g_h)[(size_t)ni * 32 + lane];
    size_t tr = (size_t)r * NN + no;
    float* dst = &g_aggh[tr * DD + lane * 4];
    atomicAdd(dst + 0, hv.x * ew);
    atomicAdd(dst + 1, hv.y * ew);
    atomicAdd(dst + 2, hv.z * ew);
    atomicAdd(dst + 3, hv.w * ew);
}

// ---------------- generic 64x128 fp32 GEMM tile (macro) ----------------
// 256 threads; warp w handles rows [w*8, w*8+8), lane handles cols [lane*4,+4)
#define GEMM_SEG(APTR, KTOT, BPTR, ROWEXPR, MROWS)                               \
    for (int k0 = 0; k0 < (KTOT); k0 += 32) {                                    \
        __syncthreads();                                                         \
        {                                                                        \
            int arow = tid >> 3;                                                 \
            int fc = (tid & 7) << 2;                                             \
            _Pragma("unroll")                                                    \
            for (int rr2 = 0; rr2 < 2; rr2++) {                                  \
                int mrow = m0 + arow + rr2 * 32;                                 \
                float4 av = make_float4(0.f, 0.f, 0.f, 0.f);                     \
                if (mrow < (MROWS)) {                                            \
                    size_t aoff = (ROWEXPR);                                     \
                    av = *(const float4*)((APTR) + aoff + k0 + fc);              \
                }                                                                \
                sA[fc + 0][arow + rr2 * 32] = av.x;                              \
                sA[fc + 1][arow + rr2 * 32] = av.y;                              \
                sA[fc + 2][arow + rr2 * 32] = av.z;                              \
                sA[fc + 3][arow + rr2 * 32] = av.w;                              \
            }                                                                    \
        }                                                                        \
        _Pragma("unroll")                                                        \
        for (int j = 0; j < 4; j++) {                                            \
            int bi = tid + j * 256;                                              \
            int kr = bi >> 5;                                                    \
            int c = (bi & 31) << 2;                                              \
            *(float4*)&sB[kr][c] = *(const float4*)((BPTR) + (size_t)(k0 + kr) * DD + c); \
        }                                                                        \
        __syncthreads();                                                         \
        _Pragma("unroll")                                                        \
        for (int kk = 0; kk < 32; kk++) {                                        \
            float4 bv = *(float4*)&sB[kk][colbase];                              \
            _Pragma("unroll")                                                    \
            for (int i = 0; i < 8; i++) {                                        \
                float a = sA[kk][rowb + i];                                      \
                acc[i].x += a * bv.x; acc[i].y += a * bv.y;                      \
                acc[i].z += a * bv.z; acc[i].w += a * bv.w;                      \
            }                                                                    \
        }                                                                        \
    }

// GEMM1: h_pre = aggx@Wlin1 + aggef@WeWlin1 + x@Wself1 + bias1 + mask*beWlin1
__global__ __launch_bounds__(256) void gemm1_k(
    const float* __restrict__ x, const float* __restrict__ Wlin1,
    const float* __restrict__ Wself1)
{
    __shared__ float sA[32][65];
    __shared__ float sB[32][128];
    __shared__ float sBe[RR * DD];
    __shared__ float sBias[DD];
    int tid = threadIdx.x;
    int m0 = blockIdx.x * 64;
    for (int i = tid; i < RR * DD; i += 256) sBe[i] = g_beWlin1[i];
    if (tid < DD) sBias[tid] = g_bias1[tid];
    int colbase = (tid & 31) << 2;
    int rowb = (tid >> 5) << 3;
    float4 acc[8];
#pragma unroll
    for (int i = 0; i < 8; i++) acc[i] = make_float4(0.f, 0.f, 0.f, 0.f);

    GEMM_SEG(g_aggx, RR * DD, Wlin1, (size_t)mrow * (RR * DD), NN)
    GEMM_SEG(g_aggef, RR * EDD, g_WeWlin1, (size_t)mrow * (RR * EDD), NN)
    GEMM_SEG(x, DD, Wself1, (size_t)mrow * DD, NN)

#pragma unroll
    for (int i = 0; i < 8; i++) {
        int m = m0 + rowb + i;
        if (m < NN) {
            float4 v = acc[i];
            v.x += sBias[colbase + 0]; v.y += sBias[colbase + 1];
            v.z += sBias[colbase + 2]; v.w += sBias[colbase + 3];
#pragma unroll
            for (int r = 0; r < RR; r++) {
                if (g_deg[m * RR + r] > 0.f) {
                    v.x += sBe[r * DD + colbase + 0];
                    v.y += sBe[r * DD + colbase + 1];
                    v.z += sBe[r * DD + colbase + 2];
                    v.w += sBe[r * DD + colbase + 3];
                }
            }
            *(float4*)&g_hpre[(size_t)m * DD + colbase] = v;
        }
    }
}

// hs = h @ l2_Wself + (l2_bself + l2_blin)
__global__ __launch_bounds__(256) void gemmhs_k(const float* __restrict__ Wself2) {
    __shared__ float sA[32][65];
    __shared__ float sB[32][128];
    __shared__ float sBias[DD];
    int tid = threadIdx.x;
    int m0 = blockIdx.x * 64;
    if (tid < DD) sBias[tid] = g_bias2[tid];
    int colbase = (tid & 31) << 2;
    int rowb = (tid >> 5) << 3;
    float4 acc[8];
#pragma unroll
    for (int i = 0; i < 8; i++) acc[i] = make_float4(0.f, 0.f, 0.f, 0.f);

    GEMM_SEG(g_h, DD, Wself2, (size_t)mrow * DD, NN)

#pragma unroll
    for (int i = 0; i < 8; i++) {
        int m = m0 + rowb + i;
        if (m < NN) {
            float4 v = acc[i];
            v.x += sBias[colbase + 0]; v.y += sBias[colbase + 1];
            v.z += sBias[colbase + 2]; v.w += sBias[colbase + 3];
            *(float4*)&g_hs[(size_t)m * DD + colbase] = v;
        }
    }
}

// GEMM2: out[m] = aggh[m]@Wlin2 + aggef[n,r]@WeWlin2 + hs[n] + mask*beWlin2
// m = r*N + n
__global__ __launch_bounds__(256) void gemm2_k(const float* __restrict__ Wlin2,
                                               float* __restrict__ out)
{
    __shared__ float sA[32][65];
    __shared__ float sB[32][128];
    __shared__ float sBe2[DD];
    int tid = threadIdx.x;
    int m0 = blockIdx.x * 64;
    if (tid < DD) sBe2[tid] = g_beWlin2[tid];
    int colbase = (tid & 31) << 2;
    int rowb = (tid >> 5) << 3;
    float4 acc[8];
#pragma unroll
    for (int i = 0; i < 8; i++) acc[i] = make_float4(0.f, 0.f, 0.f, 0.f);

    GEMM_SEG(g_aggh, DD, Wlin2, (size_t)mrow * DD, M2)
    GEMM_SEG(g_aggef, EDD, g_WeWlin2,
             ((size_t)((mrow % NN) * RR + (mrow / NN)) * EDD), M2)

#pragma unroll
    for (int i = 0; i < 8; i++) {
        int m = m0 + rowb + i;
        int r = m / NN;
        int n = m - r * NN;
        float4 v = acc[i];
        float4 hsv = *(const float4*)&g_hs[(size_t)n * DD + colbase];
        v.x += hsv.x; v.y += hsv.y; v.z += hsv.z; v.w += hsv.w;
        if (g_deg[n * RR + r] > 0.f) {
            v.x += sBe2[colbase + 0]; v.y += sBe2[colbase + 1];
            v.z += sBe2[colbase + 2]; v.w += sBe2[colbase + 3];
        }
        *(float4*)&out[(size_t)m * DD + colbase] = v;
    }
}

// ---------------- BN stats / finalize / apply ----------------
__global__ __launch_bounds__(128) void stats_k(const float* __restrict__ src_ext,
                                               int use_hpre, int rows, int sel) {
    const float* src = use_hpre ? g_hpre : src_ext;
    int d = threadIdx.x;
    int r0 = blockIdx.x * 256;
    int rend = r0 + 256;
    if (rend > rows) rend = rows;
    float a = 0.f, b = 0.f;
    for (int r = r0; r < rend; r++) {
        float v = src[(size_t)r * DD + d];
        a += v;
        b += v * v;
    }
    if (sel == 0) {
        atomicAdd(&g_s1a[d], (double)a);
        atomicAdd(&g_s2a[d], (double)b);
    } else {
        atomicAdd(&g_s1b[d], (double)a);
        atomicAdd(&g_s2b[d], (double)b);
    }
}

__global__ void bnfin_k(int sel, float nrows, const float* __restrict__ g,
                        const float* __restrict__ b) {
    int d = threadIdx.x;
    double s1 = sel ? g_s1b[d] : g_s1a[d];
    double s2 = sel ? g_s2b[d] : g_s2a[d];
    double m = s1 / (double)nrows;
    double var = s2 / (double)nrows - m * m;
    float sc = g[d] * rsqrtf((float)var + 1e-5f);
    float sh = b[d] - (float)m * sc;
    if (sel) { g_sc2[d] = sc; g_sh2[d] = sh; }
    else     { g_sc1[d] = sc; g_sh1[d] = sh; }
}

__global__ __launch_bounds__(256) void bnrelu_h_k() {
    int i = blockIdx.x * 256 + threadIdx.x;
    if (i >= NN * 32) return;
    int c = (i & 31) << 2;
    float4 v = ((const float4*)g_hpre)[i];
    v.x = fmaxf(0.f, v.x * g_sc1[c + 0] + g_sh1[c + 0]);
    v.y = fmaxf(0.f, v.y * g_sc1[c + 1] + g_sh1[c + 1]);
    v.z = fmaxf(0.f, v.z * g_sc1[c + 2] + g_sh1[c + 2]);
    v.w = fmaxf(0.f, v.w * g_sc1[c + 3] + g_sh1[c + 3]);
    ((float4*)g_h)[i] = v;
}

__global__ __launch_bounds__(256) void bnrelu_o_k(float* __restrict__ out) {
    int i = blockIdx.x * 256 + threadIdx.x;
    if (i >= M2 * 32) return;
    int c = (i & 31) << 2;
    float4 v = ((const float4*)out)[i];
    v.x = fmaxf(0.f, v.x * g_sc2[c + 0] + g_sh2[c + 0]);
    v.y = fmaxf(0.f, v.y * g_sc2[c + 1] + g_sh2[c + 1]);
    v.z = fmaxf(0.f, v.z * g_sc2[c + 2] + g_sh2[c + 2]);
    v.w = fmaxf(0.f, v.w * g_sc2[c + 3] + g_sh2[c + 3]);
    ((float4*)out)[i] = v;
}

// ---------------- launch ----------------
extern "C" void kernel_launch(void* const* d_in, const int* in_sizes, int n_in,
                              void* d_out, int out_size) {
    (void)in_sizes; (void)n_in; (void)out_size;
    const float* x        = (const float*)d_in[0];
    const int*   node_in  = (const int*)d_in[1];
    const int*   node_out = (const int*)d_in[2];
    const int*   relation = (const int*)d_in[3];
    const float* ew       = (const float*)d_in[4];
    const float* ef       = (const float*)d_in[5];
    const float* l1_Wlin  = (const float*)d_in[6];
    const float* l1_blin  = (const float*)d_in[7];
    const float* l1_Wself = (const float*)d_in[8];
    const float* l1_bself = (const float*)d_in[9];
    const float* l1_Wedge = (const float*)d_in[10];
    const float* l1_bedge = (const float*)d_in[11];
    const float* l1_g     = (const float*)d_in[12];
    const float* l1_b     = (const float*)d_in[13];
    const float* l2_Wlin  = (const float*)d_in[14];
    const float* l2_blin  = (const float*)d_in[15];
    const float* l2_Wself = (const float*)d_in[16];
    const float* l2_bself = (const float*)d_in[17];
    const float* l2_Wedge = (const float*)d_in[18];
    const float* l2_bedge = (const float*)d_in[19];
    const float* l2_g     = (const float*)d_in[20];
    const float* l2_b     = (const float*)d_in[21];
    float* out = (float*)d_out;

    zero_big_k<<<8192, 256>>>();
    zero_stats_k<<<1, 128>>>();
    prep_k<<<RR + 1, 128>>>(l1_Wedge, l1_Wlin, l1_bedge, l1_blin, l1_bself,
                            l2_Wedge, l2_Wlin, l2_bedge, l2_blin, l2_bself);
    deg_k<<<EE / 256, 256>>>(node_out, relation, ew);
    scatter1_k<<<EE / 8, 256>>>(x, node_in, node_out, relation, ew, ef);
    gemm1_k<<<(NN + 63) / 64, 256>>>(x, l1_Wlin, l1_Wself);
    stats_k<<<(NN + 255) / 256, 128>>>(nullptr, 1, NN, 0);
    bnfin_k<<<1, 128>>>(0, (float)NN, l1_g, l1_b);
    bnrelu_h_k<<<(NN * 32 + 255) / 256, 256>>>();
    gemmhs_k<<<(NN + 63) / 64, 256>>>(l2_Wself);
    scatter2_k<<<EE / 8, 256>>>(node_in, node_out, relation, ew);
    gemm2_k<<<M2 / 64, 256>>>(l2_Wlin, out);
    stats_k<<<(M2 + 255) / 256, 128>>>(out, 0, M2, 1);
    bnfin_k<<<1, 128>>>(1, (float)M2, l2_g, l2_b);
    bnrelu_o_k<<<(M2 * 32 + 255) / 256, 256>>>(out);
}

// round 2
// speedup vs baseline: 1.5808x; 1.5808x over previous
#include <cuda_runtime.h>
#include <cstdint>

#define NN 50000
#define DD 128
#define RR 8
#define EE 800000
#define EDD 32
#define NR (NN*RR)      /* 400000 */
#define M2 (RR*NN)      /* 400000 */

typedef unsigned long long u64;

// ---------------- scratch (static __device__, no allocation) ----------------
__device__ float g_deg[NR];
__device__ float g_aggef[NR*EDD];        // [N*R, 32] shared by both layers
__device__ float g_xW[(size_t)NN*RR*DD]; // [n, r, 128] = x @ Wlin1_r
__device__ float g_hpre[NN*DD];          // layer1 pre-BN accumulator
__device__ float g_h[NN*DD];
__device__ float g_hW2[NN*DD];           // h @ l2_Wlin
__device__ float g_hs[NN*DD];            // h @ l2_Wself + bias2
__device__ float g_WeWlin1[RR*EDD*DD];   // [r*32+i][128]
__device__ float g_WeWlin2[EDD*DD];
__device__ float g_beWlin1[RR*DD];
__device__ float g_beWlin2[DD];
__device__ float g_bias1[DD];            // l1_blin + l1_bself
__device__ float g_bias2[DD];            // l2_blin + l2_bself
__device__ double g_s1a[DD], g_s2a[DD], g_s1b[DD], g_s2b[DD];
__device__ float g_sc1[DD], g_sh1[DD], g_sc2[DD], g_sh2[DD];

// ---------------- packed f32x2 helpers ----------------
__device__ __forceinline__ u64 pack2(float lo, float hi) {
    u64 r; asm("mov.b64 %0, {%1, %2};" : "=l"(r) : "f"(lo), "f"(hi)); return r;
}
__device__ __forceinline__ u64 dup2(float v) {
    u64 r; asm("mov.b64 %0, {%1, %1};" : "=l"(r) : "f"(v)); return r;
}
__device__ __forceinline__ void unpack2(u64 v, float& lo, float& hi) {
    asm("mov.b64 {%0, %1}, %2;" : "=f"(lo), "=f"(hi) : "l"(v));
}
__device__ __forceinline__ void fma2(u64& d, u64 a, u64 b) {
    asm("fma.rn.f32x2 %0, %1, %2, %0;" : "+l"(d) : "l"(a), "l"(b));
}
__device__ __forceinline__ void red_add_v4(float* p, float4 v) {
    asm volatile("red.global.add.v4.f32 [%0], {%1, %2, %3, %4};"
                 :: "l"(p), "f"(v.x), "f"(v.y), "f"(v.z), "f"(v.w) : "memory");
}

// ---------------- zero ----------------
__global__ void zero_k() {
    size_t i = (size_t)blockIdx.x * blockDim.x + threadIdx.x;
    size_t stride = (size_t)gridDim.x * blockDim.x;
    float4 z = make_float4(0.f, 0.f, 0.f, 0.f);
    float4* e = (float4*)g_aggef;
    for (size_t j = i; j < (size_t)NR * EDD / 4; j += stride) e[j] = z;
    float4* h = (float4*)g_hpre;
    for (size_t j = i; j < (size_t)NN * DD / 4; j += stride) h[j] = z;
    float4* d = (float4*)g_deg;
    for (size_t j = i; j < (size_t)NR / 4; j += stride) d[j] = z;
    if (i < DD) { g_s1a[i] = 0.0; g_s2a[i] = 0.0; g_s1b[i] = 0.0; g_s2b[i] = 0.0; }
}

// ---------------- prep: fold We@Wlin, be@Wlin, biases ----------------
__global__ __launch_bounds__(128) void prep_k(
    const float* __restrict__ l1_We, const float* __restrict__ l1_Wlin,
    const float* __restrict__ l1_be, const float* __restrict__ l1_blin,
    const float* __restrict__ l1_bself,
    const float* __restrict__ l2_We, const float* __restrict__ l2_Wlin,
    const float* __restrict__ l2_be, const float* __restrict__ l2_blin,
    const float* __restrict__ l2_bself)
{
    __shared__ float sWe[EDD * DD];
    __shared__ float sbe[DD];
    int r = blockIdx.x;
    int d = threadIdx.x;
    const float* We = (r < RR) ? l1_We : l2_We;
    const float* Wl = (r < RR) ? l1_Wlin : l2_Wlin;
    const float* be = (r < RR) ? l1_be : l2_be;
    for (int i = d; i < EDD * DD; i += 128) sWe[i] = We[i];
    sbe[d] = be[d];
    __syncthreads();

    float acc[EDD];
#pragma unroll
    for (int i = 0; i < EDD; i++) acc[i] = 0.f;
    float accb = 0.f;
    int rowoff = (r < RR) ? r * DD : 0;
    for (int k = 0; k < DD; k++) {
        float wl = Wl[(size_t)(rowoff + k) * DD + d];
        accb += sbe[k] * wl;
#pragma unroll
        for (int i = 0; i < EDD; i++) acc[i] += sWe[i * DD + k] * wl;
    }
    if (r < RR) {
#pragma unroll
        for (int i = 0; i < EDD; i++) g_WeWlin1[(size_t)(r * EDD + i) * DD + d] = acc[i];
        g_beWlin1[r * DD + d] = accb;
    } else {
#pragma unroll
        for (int i = 0; i < EDD; i++) g_WeWlin2[(size_t)i * DD + d] = acc[i];
        g_beWlin2[d] = accb;
        g_bias1[d] = l1_blin[d] + l1_bself[d];
        g_bias2[d] = l2_blin[d] + l2_bself[d];
    }
}

// ---------------- degree ----------------
__global__ void deg_k(const int* __restrict__ nout, const int* __restrict__ rel,
                      const float* __restrict__ w) {
    int e = blockIdx.x * blockDim.x + threadIdx.x;
    if (e < EE) atomicAdd(&g_deg[nout[e] * RR + rel[e]], w[e]);
}

// ---------------- GEMM tile: 64 rows x 128 cols, 256 threads, f32x2 FMA ----
#define GEMM_SEG(APTR, KTOT, BPTR, ROWEXPR, MROWS)                               \
    for (int k0 = 0; k0 < (KTOT); k0 += 32) {                                    \
        __syncthreads();                                                         \
        {                                                                        \
            int arow = tid >> 3;                                                 \
            int fc = (tid & 7) << 2;                                             \
            _Pragma("unroll")                                                    \
            for (int rr2 = 0; rr2 < 2; rr2++) {                                  \
                int mrow = m0 + arow + rr2 * 32;                                 \
                float4 av = make_float4(0.f, 0.f, 0.f, 0.f);                     \
                if (mrow < (MROWS)) {                                            \
                    size_t aoff = (ROWEXPR);                                     \
                    av = *(const float4*)((APTR) + aoff + k0 + fc);              \
                }                                                                \
                sA[fc + 0][arow + rr2 * 32] = av.x;                              \
                sA[fc + 1][arow + rr2 * 32] = av.y;                              \
                sA[fc + 2][arow + rr2 * 32] = av.z;                              \
                sA[fc + 3][arow + rr2 * 32] = av.w;                              \
            }                                                                    \
        }                                                                        \
        _Pragma("unroll")                                                        \
        for (int j = 0; j < 4; j++) {                                            \
            int bi = tid + j * 256;                                              \
            int kr = bi >> 5;                                                    \
            int c = (bi & 31) << 2;                                              \
            *(float4*)&sB[kr][c] = *(const float4*)((BPTR) + (size_t)(k0 + kr) * DD + c); \
        }                                                                        \
        __syncthreads();                                                         \
        _Pragma("unroll")                                                        \
        for (int kk = 0; kk < 32; kk++) {                                        \
            float4 bv = *(float4*)&sB[kk][colbase];                              \
            u64 b0 = dup2(bv.x), b1 = dup2(bv.y), b2 = dup2(bv.z), b3 = dup2(bv.w); \
            float4 a0 = *(float4*)&sA[kk][rowb];                                 \
            float4 a1 = *(float4*)&sA[kk][rowb + 4];                             \
            u64 p0 = pack2(a0.x, a0.y), p1 = pack2(a0.z, a0.w);                  \
            u64 p2 = pack2(a1.x, a1.y), p3 = pack2(a1.z, a1.w);                  \
            fma2(acc[0][0], p0, b0); fma2(acc[0][1], p0, b1);                    \
            fma2(acc[0][2], p0, b2); fma2(acc[0][3], p0, b3);                    \
            fma2(acc[1][0], p1, b0); fma2(acc[1][1], p1, b1);                    \
            fma2(acc[1][2], p1, b2); fma2(acc[1][3], p1, b3);                    \
            fma2(acc[2][0], p2, b0); fma2(acc[2][1], p2, b1);                    \
            fma2(acc[2][2], p2, b2); fma2(acc[2][3], p2, b3);                    \
            fma2(acc[3][0], p3, b0); fma2(acc[3][1], p3, b1);                    \
            fma2(acc[3][2], p3, b2); fma2(acc[3][3], p3, b3);                    \
        }                                                                        \
    }

#define GEMM_PROLOG()                                                            \
    int tid = threadIdx.x;                                                       \
    int m0 = blockIdx.x * 64;                                                    \
    int colbase = (tid & 31) << 2;                                               \
    int rowb = (tid >> 5) << 3;                                                  \
    u64 acc[4][4];                                                               \
    _Pragma("unroll")                                                            \
    for (int i = 0; i < 4; i++) { acc[i][0] = 0; acc[i][1] = 0; acc[i][2] = 0; acc[i][3] = 0; }

#define UNPACK_ROWS(VR)                                                          \
    float4 VR[8];                                                                \
    _Pragma("unroll")                                                            \
    for (int i = 0; i < 4; i++) {                                                \
        unpack2(acc[i][0], VR[2*i].x, VR[2*i+1].x);                              \
        unpack2(acc[i][1], VR[2*i].y, VR[2*i+1].y);                              \
        unpack2(acc[i][2], VR[2*i].z, VR[2*i+1].z);                              \
        unpack2(acc[i][3], VR[2*i].w, VR[2*i+1].w);                              \
    }

// ---------------- xW = x @ Wlin1_r  (per relation block) ----------------
__global__ __launch_bounds__(256) void xw_k(const float* __restrict__ x,
                                            const float* __restrict__ Wlin1) {
    __shared__ __align__(16) float sA[32][68];
    __shared__ __align__(16) float sB[32][128];
    int rsel = blockIdx.y;
    GEMM_PROLOG()
    const float* B = Wlin1 + (size_t)rsel * DD * DD;
    GEMM_SEG(x, DD, B, (size_t)mrow * DD, NN)
    UNPACK_ROWS(vr)
#pragma unroll
    for (int j = 0; j < 8; j++) {
        int m = m0 + rowb + j;
        if (m < NN)
            *(float4*)&g_xW[(size_t)m * (RR * DD) + rsel * DD + colbase] = vr[j];
    }
}

// ---------------- scatter layer 1 ----------------
__global__ __launch_bounds__(256) void scatter1_k(
    const int* __restrict__ nin, const int* __restrict__ nout,
    const int* __restrict__ rel, const float* __restrict__ w,
    const float* __restrict__ ef)
{
    int idx = blockIdx.x * 256 + threadIdx.x;
    int e = idx >> 5;
    int lane = idx & 31;
    if (e >= EE) return;
    int ni = __ldg(nin + e);
    int no = __ldg(nout + e);
    int r  = __ldg(rel + e);
    int nor = no * RR + r;
    float ew = __ldg(w + e) / g_deg[nor];

    float4 xv = *(const float4*)&g_xW[(size_t)ni * (RR * DD) + r * DD + lane * 4];
    xv.x *= ew; xv.y *= ew; xv.z *= ew; xv.w *= ew;
    red_add_v4(&g_hpre[(size_t)no * DD + lane * 4], xv);

    float ev = __ldg(ef + (size_t)e * EDD + lane) * ew;
    atomicAdd(&g_aggef[(size_t)nor * EDD + lane], ev);
}

// ---------------- gemm1: hpre += aggef@WeWlin1 + x@Wself1 + biases; stats --
__global__ __launch_bounds__(256) void gemm1_k(const float* __restrict__ x,
                                               const float* __restrict__ Wself1) {
    __shared__ __align__(16) float sA[32][68];
    __shared__ __align__(16) float sB[32][128];
    __shared__ float sBe[RR * DD];
    __shared__ float sBias[DD];
    __shared__ float sRed[2][DD];
    GEMM_PROLOG()
    for (int i = tid; i < RR * DD; i += 256) sBe[i] = g_beWlin1[i];
    if (tid < DD) { sBias[tid] = g_bias1[tid]; sRed[0][tid] = 0.f; sRed[1][tid] = 0.f; }

    GEMM_SEG(g_aggef, RR * EDD, g_WeWlin1, (size_t)mrow * (RR * EDD), NN)
    GEMM_SEG(x, DD, Wself1, (size_t)mrow * DD, NN)

    UNPACK_ROWS(vr)
    float4 la = make_float4(0.f, 0.f, 0.f, 0.f);
    float4 lb = make_float4(0.f, 0.f, 0.f, 0.f);
#pragma unroll
    for (int j = 0; j < 8; j++) {
        int m = m0 + rowb + j;
        if (m < NN) {
            float4 v = vr[j];
            float4 sc = *(const float4*)&g_hpre[(size_t)m * DD + colbase];
            v.x += sc.x + sBias[colbase + 0];
            v.y += sc.y + sBias[colbase + 1];
            v.z += sc.z + sBias[colbase + 2];
            v.w += sc.w + sBias[colbase + 3];
#pragma unroll
            for (int r = 0; r < RR; r++) {
                if (g_deg[m * RR + r] > 0.f) {
                    v.x += sBe[r * DD + colbase + 0];
                    v.y += sBe[r * DD + colbase + 1];
                    v.z += sBe[r * DD + colbase + 2];
                    v.w += sBe[r * DD + colbase + 3];
                }
            }
            *(float4*)&g_hpre[(size_t)m * DD + colbase] = v;
            la.x += v.x; la.y += v.y; la.z += v.z; la.w += v.w;
            lb.x += v.x * v.x; lb.y += v.y * v.y; lb.z += v.z * v.z; lb.w += v.w * v.w;
        }
    }
    atomicAdd(&sRed[0][colbase + 0], la.x); atomicAdd(&sRed[0][colbase + 1], la.y);
    atomicAdd(&sRed[0][colbase + 2], la.z); atomicAdd(&sRed[0][colbase + 3], la.w);
    atomicAdd(&sRed[1][colbase + 0], lb.x); atomicAdd(&sRed[1][colbase + 1], lb.y);
    atomicAdd(&sRed[1][colbase + 2], lb.z); atomicAdd(&sRed[1][colbase + 3], lb.w);
    __syncthreads();
    if (tid < DD) {
        atomicAdd(&g_s1a[tid], (double)sRed[0][tid]);
        atomicAdd(&g_s2a[tid], (double)sRed[1][tid]);
    }
}

// ---------------- h2: hW2 = h@Wlin2 (y=0) ; hs = h@Wself2 + bias2 (y=1) ----
__global__ __launch_bounds__(256) void h2_k(const float* __restrict__ Wlin2,
                                            const float* __restrict__ Wself2) {
    __shared__ __align__(16) float sA[32][68];
    __shared__ __align__(16) float sB[32][128];
    __shared__ float sBias[DD];
    int ysel = blockIdx.y;
    GEMM_PROLOG()
    if (tid < DD) sBias[tid] = g_bias2[tid];
    const float* B = ysel ? Wself2 : Wlin2;
    GEMM_SEG(g_h, DD, B, (size_t)mrow * DD, NN)
    UNPACK_ROWS(vr)
    float* dst = ysel ? g_hs : g_hW2;
#pragma unroll
    for (int j = 0; j < 8; j++) {
        int m = m0 + rowb + j;
        if (m < NN) {
            float4 v = vr[j];
            if (ysel) {
                v.x += sBias[colbase + 0]; v.y += sBias[colbase + 1];
                v.z += sBias[colbase + 2]; v.w += sBias[colbase + 3];
            }
            *(float4*)&dst[(size_t)m * DD + colbase] = v;
        }
    }
}

// ---------------- init out[r*N+n] = hs[n] + mask*beWlin2 ----------------
__global__ __launch_bounds__(256) void init_out_k(float* __restrict__ out) {
    int i = blockIdx.x * 256 + threadIdx.x;
    if (i >= M2 * 32) return;
    int m = i >> 5;
    int c4 = (i & 31) << 2;
    int r = m / NN;
    int n = m - r * NN;
    float4 v = *(const float4*)&g_hs[(size_t)n * DD + c4];
    if (g_deg[n * RR + r] > 0.f) {
        v.x += g_beWlin2[c4 + 0]; v.y += g_beWlin2[c4 + 1];
        v.z += g_beWlin2[c4 + 2]; v.w += g_beWlin2[c4 + 3];
    }
    *(float4*)&out[(size_t)m * DD + c4] = v;
}

// ---------------- scatter layer 2: directly into out [R,N,128] -----------
__global__ __launch_bounds__(256) void scatter2_k(
    const int* __restrict__ nin, const int* __restrict__ nout,
    const int* __restrict__ rel, const float* __restrict__ w,
    float* __restrict__ out)
{
    int idx = blockIdx.x * 256 + threadIdx.x;
    int e = idx >> 5;
    int lane = idx & 31;
    if (e >= EE) return;
    int ni = __ldg(nin + e);
    int no = __ldg(nout + e);
    int r  = __ldg(rel + e);
    int nor = no * RR + r;
    float ew = __ldg(w + e) / g_deg[nor];

    float4 hv = *(const float4*)&g_hW2[(size_t)ni * DD + lane * 4];
    hv.x *= ew; hv.y *= ew; hv.z *= ew; hv.w *= ew;
    red_add_v4(&out[((size_t)r * NN + no) * DD + lane * 4], hv);
}

// ---------------- ef2: out += aggef@WeWlin2 ; stats ----------------
__global__ __launch_bounds__(256) void ef2_k(float* __restrict__ out) {
    __shared__ __align__(16) float sA[32][68];
    __shared__ __align__(16) float sB[32][128];
    __shared__ float sRed[2][DD];
    GEMM_PROLOG()
    if (tid < DD) { sRed[0][tid] = 0.f; sRed[1][tid] = 0.f; }

    GEMM_SEG(g_aggef, EDD, g_WeWlin2,
             (size_t)((mrow % NN) * RR + (mrow / NN)) * EDD, M2)

    UNPACK_ROWS(vr)
    float4 la = make_float4(0.f, 0.f, 0.f, 0.f);
    float4 lb = make_float4(0.f, 0.f, 0.f, 0.f);
#pragma unroll
    for (int j = 0; j < 8; j++) {
        int m = m0 + rowb + j;
        if (m < M2) {
            float4 v = vr[j];
            float4 sc = *(const float4*)&out[(size_t)m * DD + colbase];
            v.x += sc.x; v.y += sc.y; v.z += sc.z; v.w += sc.w;
            *(float4*)&out[(size_t)m * DD + colbase] = v;
            la.x += v.x; la.y += v.y; la.z += v.z; la.w += v.w;
            lb.x += v.x * v.x; lb.y += v.y * v.y; lb.z += v.z * v.z; lb.w += v.w * v.w;
        }
    }
    atomicAdd(&sRed[0][colbase + 0], la.x); atomicAdd(&sRed[0][colbase + 1], la.y);
    atomicAdd(&sRed[0][colbase + 2], la.z); atomicAdd(&sRed[0][colbase + 3], la.w);
    atomicAdd(&sRed[1][colbase + 0], lb.x); atomicAdd(&sRed[1][colbase + 1], lb.y);
    atomicAdd(&sRed[1][colbase + 2], lb.z); atomicAdd(&sRed[1][colbase + 3], lb.w);
    __syncthreads();
    if (tid < DD) {
        atomicAdd(&g_s1b[tid], (double)sRed[0][tid]);
        atomicAdd(&g_s2b[tid], (double)sRed[1][tid]);
    }
}

// ---------------- BN finalize / apply ----------------
__global__ void bnfin_k(int sel, float nrows, const float* __restrict__ g,
                        const float* __restrict__ b) {
    int d = threadIdx.x;
    double s1 = sel ? g_s1b[d] : g_s1a[d];
    double s2 = sel ? g_s2b[d] : g_s2a[d];
    double m = s1 / (double)nrows;
    double var = s2 / (double)nrows - m * m;
    float sc = g[d] * rsqrtf((float)var + 1e-5f);
    float sh = b[d] - (float)m * sc;
    if (sel) { g_sc2[d] = sc; g_sh2[d] = sh; }
    else     { g_sc1[d] = sc; g_sh1[d] = sh; }
}

__global__ __launch_bounds__(256) void bnrelu_h_k() {
    int i = blockIdx.x * 256 + threadIdx.x;
    if (i >= NN * 32) return;
    int c = (i & 31) << 2;
    float4 v = ((const float4*)g_hpre)[i];
    v.x = fmaxf(0.f, v.x * g_sc1[c + 0] + g_sh1[c + 0]);
    v.y = fmaxf(0.f, v.y * g_sc1[c + 1] + g_sh1[c + 1]);
    v.z = fmaxf(0.f, v.z * g_sc1[c + 2] + g_sh1[c + 2]);
    v.w = fmaxf(0.f, v.w * g_sc1[c + 3] + g_sh1[c + 3]);
    ((float4*)g_h)[i] = v;
}

__global__ __launch_bounds__(256) void bnrelu_o_k(float* __restrict__ out) {
    int i = blockIdx.x * 256 + threadIdx.x;
    if (i >= M2 * 32) return;
    int c = (i & 31) << 2;
    float4 v = ((const float4*)out)[i];
    v.x = fmaxf(0.f, v.x * g_sc2[c + 0] + g_sh2[c + 0]);
    v.y = fmaxf(0.f, v.y * g_sc2[c + 1] + g_sh2[c + 1]);
    v.z = fmaxf(0.f, v.z * g_sc2[c + 2] + g_sh2[c + 2]);
    v.w = fmaxf(0.f, v.w * g_sc2[c + 3] + g_sh2[c + 3]);
    ((float4*)out)[i] = v;
}

// ---------------- launch ----------------
extern "C" void kernel_launch(void* const* d_in, const int* in_sizes, int n_in,
                              void* d_out, int out_size) {
    (void)in_sizes; (void)n_in; (void)out_size;
    const float* x        = (const float*)d_in[0];
    const int*   node_in  = (const int*)d_in[1];
    const int*   node_out = (const int*)d_in[2];
    const int*   relation = (const int*)d_in[3];
    const float* ew       = (const float*)d_in[4];
    const float* ef       = (const float*)d_in[5];
    const float* l1_Wlin  = (const float*)d_in[6];
    const float* l1_blin  = (const float*)d_in[7];
    const float* l1_Wself = (const float*)d_in[8];
    const float* l1_bself = (const float*)d_in[9];
    const float* l1_Wedge = (const float*)d_in[10];
    const float* l1_bedge = (const float*)d_in[11];
    const float* l1_g     = (const float*)d_in[12];
    const float* l1_b     = (const float*)d_in[13];
    const float* l2_Wlin  = (const float*)d_in[14];
    const float* l2_blin  = (const float*)d_in[15];
    const float* l2_Wself = (const float*)d_in[16];
    const float* l2_bself = (const float*)d_in[17];
    const float* l2_Wedge = (const float*)d_in[18];
    const float* l2_bedge = (const float*)d_in[19];
    const float* l2_g     = (const float*)d_in[20];
    const float* l2_b     = (const float*)d_in[21];
    float* out = (float*)d_out;

    int gm1 = (NN + 63) / 64;   // 782

    zero_k<<<4096, 256>>>();
    prep_k<<<RR + 1, 128>>>(l1_Wedge, l1_Wlin, l1_bedge, l1_blin, l1_bself,
                            l2_Wedge, l2_Wlin, l2_bedge, l2_blin, l2_bself);
    deg_k<<<EE / 256, 256>>>(node_out, relation, ew);
    xw_k<<<dim3(gm1, RR), 256>>>(x, l1_Wlin);
    scatter1_k<<<EE / 8, 256>>>(node_in, node_out, relation, ew, ef);
    gemm1_k<<<gm1, 256>>>(x, l1_Wself);
    bnfin_k<<<1, 128>>>(0, (float)NN, l1_g, l1_b);
    bnrelu_h_k<<<(NN * 32 + 255) / 256, 256>>>();
    h2_k<<<dim3(gm1, 2), 256>>>(l2_Wlin, l2_Wself);
    init_out_k<<<(M2 * 32) / 256, 256>>>(out);
    scatter2_k<<<EE / 8, 256>>>(node_in, node_out, relation, ew, out);
    ef2_k<<<M2 / 64, 256>>>(out);
    bnfin_k<<<1, 128>>>(1, (float)M2, l2_g, l2_b);
    bnrelu_o_k<<<(M2 * 32) / 256, 256>>>(out);
}

// round 4
// speedup vs baseline: 1.6541x; 1.0464x over previous
#include <cuda_runtime.h>
#include <cstdint>

#define NN 50000
#define DD 128
#define RR 8
#define EE 800000
#define EDD 32
#define NR (NN*RR)
#define M2 (RR*NN)

typedef unsigned long long u64;

// ---------------- scratch ----------------
__device__ float g_deg[NR];
__device__ float g_aggef[NR*EDD];
__device__ float g_xW[(size_t)NN*RR*DD];  // [n, r, 128]
__device__ float g_hpre[NN*DD];
__device__ float g_hW2[NN*DD];
__device__ float g_hs[NN*DD];
__device__ float g_WeWlin1[RR*EDD*DD];
__device__ float g_WeWlin2[EDD*DD];
__device__ float g_beWlin1[RR*DD];
__device__ float g_beWlin2[DD];
__device__ float g_bias1[DD];
__device__ float g_bias2[DD];
__device__ double g_s1a[DD], g_s2a[DD], g_s1b[DD], g_s2b[DD];
__device__ float g_sc1[DD], g_sh1[DD], g_sc2[DD], g_sh2[DD];

// ---------------- helpers ----------------
__device__ __forceinline__ u64 pack2(float lo, float hi) {
    u64 r; asm("mov.b64 %0, {%1, %2};" : "=l"(r) : "f"(lo), "f"(hi)); return r;
}
__device__ __forceinline__ u64 dup2(float v) {
    u64 r; asm("mov.b64 %0, {%1, %1};" : "=l"(r) : "f"(v)); return r;
}
__device__ __forceinline__ void unpack2(u64 v, float& lo, float& hi) {
    asm("mov.b64 {%0, %1}, %2;" : "=f"(lo), "=f"(hi) : "l"(v));
}
__device__ __forceinline__ void fma2(u64& d, u64 a, u64 b) {
    asm("fma.rn.f32x2 %0, %1, %2, %0;" : "+l"(d) : "l"(a), "l"(b));
}
__device__ __forceinline__ void red_add_v4(float* p, float4 v) {
    asm volatile("red.global.add.v4.f32 [%0], {%1, %2, %3, %4};"
                 :: "l"(p), "f"(v.x), "f"(v.y), "f"(v.z), "f"(v.w) : "memory");
}
__device__ __forceinline__ uint32_t f2tf32(float f) {
    uint32_t r; asm("cvt.rna.tf32.f32 %0, %1;" : "=r"(r) : "f"(f)); return r;
}
__device__ __forceinline__ void mma_tf32(float* d, const uint32_t* a,
                                         uint32_t b0, uint32_t b1) {
    asm volatile(
        "mma.sync.aligned.m16n8k8.row.col.f32.tf32.tf32.f32 "
        "{%0,%1,%2,%3}, {%4,%5,%6,%7}, {%8,%9}, {%0,%1,%2,%3};"
        : "+f"(d[0]), "+f"(d[1]), "+f"(d[2]), "+f"(d[3])
        : "r"(a[0]), "r"(a[1]), "r"(a[2]), "r"(a[3]), "r"(b0), "r"(b1));
}

// ---------------- zero ----------------
__global__ void zero_k() {
    size_t i = (size_t)blockIdx.x * blockDim.x + threadIdx.x;
    size_t stride = (size_t)gridDim.x * blockDim.x;
    float4 z = make_float4(0.f, 0.f, 0.f, 0.f);
    float4* e = (float4*)g_aggef;
    for (size_t j = i; j < (size_t)NR * EDD / 4; j += stride) e[j] = z;
    float4* h = (float4*)g_hpre;
    for (size_t j = i; j < (size_t)NN * DD / 4; j += stride) h[j] = z;
    float4* d = (float4*)g_deg;
    for (size_t j = i; j < (size_t)NR / 4; j += stride) d[j] = z;
    if (i < DD) { g_s1a[i] = 0.0; g_s2a[i] = 0.0; g_s1b[i] = 0.0; g_s2b[i] = 0.0; }
}

// ---------------- prep: folds ----------------
__global__ __launch_bounds__(128) void prep_k(
    const float* __restrict__ l1_We, const float* __restrict__ l1_Wlin,
    const float* __restrict__ l1_be, const float* __restrict__ l1_blin,
    const float* __restrict__ l1_bself,
    const float* __restrict__ l2_We, const float* __restrict__ l2_Wlin,
    const float* __restrict__ l2_be, const float* __restrict__ l2_blin,
    const float* __restrict__ l2_bself)
{
    __shared__ float sWe[EDD * DD];
    __shared__ float sbe[DD];
    int r = blockIdx.x;
    int d = threadIdx.x;
    const float* We = (r < RR) ? l1_We : l2_We;
    const float* Wl = (r < RR) ? l1_Wlin : l2_Wlin;
    const float* be = (r < RR) ? l1_be : l2_be;
    for (int i = d; i < EDD * DD; i += 128) sWe[i] = We[i];
    sbe[d] = be[d];
    __syncthreads();
    float acc[EDD];
#pragma unroll
    for (int i = 0; i < EDD; i++) acc[i] = 0.f;
    float accb = 0.f;
    int rowoff = (r < RR) ? r * DD : 0;
    for (int k = 0; k < DD; k++) {
        float wl = Wl[(size_t)(rowoff + k) * DD + d];
        accb += sbe[k] * wl;
#pragma unroll
        for (int i = 0; i < EDD; i++) acc[i] += sWe[i * DD + k] * wl;
    }
    if (r < RR) {
#pragma unroll
        for (int i = 0; i < EDD; i++) g_WeWlin1[(size_t)(r * EDD + i) * DD + d] = acc[i];
        g_beWlin1[r * DD + d] = accb;
    } else {
#pragma unroll
        for (int i = 0; i < EDD; i++) g_WeWlin2[(size_t)i * DD + d] = acc[i];
        g_beWlin2[d] = accb;
        g_bias1[d] = l1_blin[d] + l1_bself[d];
        g_bias2[d] = l2_blin[d] + l2_bself[d];
    }
}

// ---------------- degree ----------------
__global__ void deg_k(const int* __restrict__ nout, const int* __restrict__ rel,
                      const float* __restrict__ w) {
    int e = blockIdx.x * blockDim.x + threadIdx.x;
    if (e < EE) atomicAdd(&g_deg[nout[e] * RR + rel[e]], w[e]);
}

// ---------------- xw via mma.sync tf32 ----------------
// xW[m, r*128+c] = sum_k x[m,k] * Wlin1[r*128+k, c]
// CTA: 128 rows x 128 cols (one relation), 8 warps (4m x 2n), warp 32x64.
#define XPAD 132
#define XW_SMEM_BYTES (2 * 128 * XPAD * 4)

__global__ void __launch_bounds__(256) xw_mma_k(const float* __restrict__ x,
                                                const float* __restrict__ Wlin1) {
    extern __shared__ uint32_t sm[];
    uint32_t* sA = sm;                  // [128][XPAD] tf32 of x tile
    uint32_t* sB = sm + 128 * XPAD;     // [128][XPAD] tf32 of Wlin1_r (k-major)
    int tid = threadIdx.x;
    int m0 = blockIdx.x * 128;
    int r = blockIdx.y;

    const float* Wr = Wlin1 + (size_t)r * DD * DD;
    for (int i = tid; i < 4096; i += 256) {
        int row = i >> 5;
        int c4 = (i & 31) << 2;
        float4 av = make_float4(0.f, 0.f, 0.f, 0.f);
        int m = m0 + row;
        if (m < NN) av = *(const float4*)&x[(size_t)m * DD + c4];
        uint32_t* da = &sA[row * XPAD + c4];
        da[0] = f2tf32(av.x); da[1] = f2tf32(av.y);
        da[2] = f2tf32(av.z); da[3] = f2tf32(av.w);
        float4 bv = *(const float4*)&Wr[(size_t)row * DD + c4];
        uint32_t* db = &sB[row * XPAD + c4];
        db[0] = f2tf32(bv.x); db[1] = f2tf32(bv.y);
        db[2] = f2tf32(bv.z); db[3] = f2tf32(bv.w);
    }
    __syncthreads();

    int wid = tid >> 5;
    int lane = tid & 31;
    int g = lane >> 2;
    int t = lane & 3;
    int wm = (wid & 3) * 32;
    int wn = (wid >> 2) * 64;

    float acc[2][8][4];
#pragma unroll
    for (int mi = 0; mi < 2; mi++)
#pragma unroll
        for (int ni = 0; ni < 8; ni++) {
            acc[mi][ni][0] = 0.f; acc[mi][ni][1] = 0.f;
            acc[mi][ni][2] = 0.f; acc[mi][ni][3] = 0.f;
        }

#pragma unroll 4
    for (int k0 = 0; k0 < 128; k0 += 8) {
        uint32_t a[2][4];
#pragma unroll
        for (int mi = 0; mi < 2; mi++) {
            int bm = wm + mi * 16;
            a[mi][0] = sA[(bm + g) * XPAD + k0 + t];
            a[mi][1] = sA[(bm + g + 8) * XPAD + k0 + t];
            a[mi][2] = sA[(bm + g) * XPAD + k0 + t + 4];
            a[mi][3] = sA[(bm + g + 8) * XPAD + k0 + t + 4];
        }
#pragma unroll
        for (int ni = 0; ni < 8; ni++) {
            int bn = wn + ni * 8;
            uint32_t b0 = sB[(k0 + t) * XPAD + bn + g];
            uint32_t b1 = sB[(k0 + t + 4) * XPAD + bn + g];
            mma_tf32(acc[0][ni], a[0], b0, b1);
            mma_tf32(acc[1][ni], a[1], b0, b1);
        }
    }

    // epilogue: D rows (g, g+8) of each 16-row tile, cols 2t, 2t+1
#pragma unroll
    for (int mi = 0; mi < 2; mi++) {
#pragma unroll
        for (int ni = 0; ni < 8; ni++) {
            int mg = m0 + wm + mi * 16 + g;
            int cb = r * DD + wn + ni * 8 + 2 * t;
            if (mg < NN)
                *(float2*)&g_xW[(size_t)mg * (RR * DD) + cb] =
                    make_float2(acc[mi][ni][0], acc[mi][ni][1]);
            if (mg + 8 < NN)
                *(float2*)&g_xW[(size_t)(mg + 8) * (RR * DD) + cb] =
                    make_float2(acc[mi][ni][2], acc[mi][ni][3]);
        }
    }
}

// ---------------- scatter layer 1 ----------------
__global__ __launch_bounds__(256) void scatter1_k(
    const int* __restrict__ nin, const int* __restrict__ nout,
    const int* __restrict__ rel, const float* __restrict__ w,
    const float* __restrict__ ef)
{
    int idx = blockIdx.x * 256 + threadIdx.x;
    int e = idx >> 5;
    int lane = idx & 31;
    if (e >= EE) return;
    int ni = __ldg(nin + e);
    int no = __ldg(nout + e);
    int r  = __ldg(rel + e);
    int nor = no * RR + r;
    float ew = __ldg(w + e) / g_deg[nor];

    float4 xv = *(const float4*)&g_xW[(size_t)ni * (RR * DD) + r * DD + lane * 4];
    xv.x *= ew; xv.y *= ew; xv.z *= ew; xv.w *= ew;
    red_add_v4(&g_hpre[(size_t)no * DD + lane * 4], xv);

    if (lane < 8) {
        float4 ev = *(const float4*)&ef[(size_t)e * EDD + lane * 4];
        ev.x *= ew; ev.y *= ew; ev.z *= ew; ev.w *= ew;
        red_add_v4(&g_aggef[(size_t)nor * EDD + lane * 4], ev);
    }
}

// ---------------- GEMM tile macros (fp32, f32x2) ----------------
#define GEMM_SEG(APTR, KTOT, BPTR, ROWEXPR, MROWS)                               \
    for (int k0 = 0; k0 < (KTOT); k0 += 32) {                                    \
        __syncthreads();                                                         \
        {                                                                        \
            int arow = tid >> 3;                                                 \
            int fc = (tid & 7) << 2;                                             \
            _Pragma("unroll")                                                    \
            for (int rr2 = 0; rr2 < 2; rr2++) {                                  \
                int mrow = m0 + arow + rr2 * 32;                                 \
                float4 av = make_float4(0.f, 0.f, 0.f, 0.f);                     \
                if (mrow < (MROWS)) {                                            \
                    size_t aoff = (ROWEXPR);                                     \
                    av = *(const float4*)((APTR) + aoff + k0 + fc);              \
                }                                                                \
                sA[fc + 0][arow + rr2 * 32] = av.x;                              \
                sA[fc + 1][arow + rr2 * 32] = av.y;                              \
                sA[fc + 2][arow + rr2 * 32] = av.z;                              \
                sA[fc + 3][arow + rr2 * 32] = av.w;                              \
            }                                                                    \
        }                                                                        \
        _Pragma("unroll")                                                        \
        for (int j = 0; j < 4; j++) {                                            \
            int bi = tid + j * 256;                                              \
            int kr = bi >> 5;                                                    \
            int c = (bi & 31) << 2;                                              \
            *(float4*)&sB[kr][c] = *(const float4*)((BPTR) + (size_t)(k0 + kr) * DD + c); \
        }                                                                        \
        __syncthreads();                                                         \
        _Pragma("unroll")                                                        \
        for (int kk = 0; kk < 32; kk++) {                                        \
            float4 bv = *(float4*)&sB[kk][colbase];                              \
            u64 b0 = dup2(bv.x), b1 = dup2(bv.y), b2 = dup2(bv.z), b3 = dup2(bv.w); \
            float4 a0 = *(float4*)&sA[kk][rowb];                                 \
            float4 a1 = *(float4*)&sA[kk][rowb + 4];                             \
            u64 p0 = pack2(a0.x, a0.y), p1 = pack2(a0.z, a0.w);                  \
            u64 p2 = pack2(a1.x, a1.y), p3 = pack2(a1.z, a1.w);                  \
            fma2(acc[0][0], p0, b0); fma2(acc[0][1], p0, b1);                    \
            fma2(acc[0][2], p0, b2); fma2(acc[0][3], p0, b3);                    \
            fma2(acc[1][0], p1, b0); fma2(acc[1][1], p1, b1);                    \
            fma2(acc[1][2], p1, b2); fma2(acc[1][3], p1, b3);                    \
            fma2(acc[2][0], p2, b0); fma2(acc[2][1], p2, b1);                    \
            fma2(acc[2][2], p2, b2); fma2(acc[2][3], p2, b3);                    \
            fma2(acc[3][0], p3, b0); fma2(acc[3][1], p3, b1);                    \
            fma2(acc[3][2], p3, b2); fma2(acc[3][3], p3, b3);                    \
        }                                                                        \
    }

#define GEMM_SEG_BN(APTR, KTOT, BPTR, ROWEXPR, MROWS)                            \
    for (int k0 = 0; k0 < (KTOT); k0 += 32) {                                    \
        __syncthreads();                                                         \
        {                                                                        \
            int arow = tid >> 3;                                                 \
            int fc = (tid & 7) << 2;                                             \
            _Pragma("unroll")                                                    \
            for (int rr2 = 0; rr2 < 2; rr2++) {                                  \
                int mrow = m0 + arow + rr2 * 32;                                 \
                float4 av = make_float4(0.f, 0.f, 0.f, 0.f);                     \
                if (mrow < (MROWS)) {                                            \
                    size_t aoff = (ROWEXPR);                                     \
                    av = *(const float4*)((APTR) + aoff + k0 + fc);              \
                    av.x = fmaxf(0.f, av.x * sSc[k0 + fc + 0] + sSh[k0 + fc + 0]); \
                    av.y = fmaxf(0.f, av.y * sSc[k0 + fc + 1] + sSh[k0 + fc + 1]); \
                    av.z = fmaxf(0.f, av.z * sSc[k0 + fc + 2] + sSh[k0 + fc + 2]); \
                    av.w = fmaxf(0.f, av.w * sSc[k0 + fc + 3] + sSh[k0 + fc + 3]); \
                }                                                                \
                sA[fc + 0][arow + rr2 * 32] = av.x;                              \
                sA[fc + 1][arow + rr2 * 32] = av.y;                              \
                sA[fc + 2][arow + rr2 * 32] = av.z;                              \
                sA[fc + 3][arow + rr2 * 32] = av.w;                              \
            }                                                                    \
        }                                                                        \
        _Pragma("unroll")                                                        \
        for (int j = 0; j < 4; j++) {                                            \
            int bi = tid + j * 256;                                              \
            int kr = bi >> 5;                                                    \
            int c = (bi & 31) << 2;                                              \
            *(float4*)&sB[kr][c] = *(const float4*)((BPTR) + (size_t)(k0 + kr) * DD + c); \
        }                                                                        \
        __syncthreads();                                                         \
        _Pragma("unroll")                                                        \
        for (int kk = 0; kk < 32; kk++) {                                        \
            float4 bv = *(float4*)&sB[kk][colbase];                              \
            u64 b0 = dup2(bv.x), b1 = dup2(bv.y), b2 = dup2(bv.z), b3 = dup2(bv.w); \
            float4 a0 = *(float4*)&sA[kk][rowb];                                 \
            float4 a1 = *(float4*)&sA[kk][rowb + 4];                             \
            u64 p0 = pack2(a0.x, a0.y), p1 = pack2(a0.z, a0.w);                  \
            u64 p2 = pack2(a1.x, a1.y), p3 = pack2(a1.z, a1.w);                  \
            fma2(acc[0][0], p0, b0); fma2(acc[0][1], p0, b1);                    \
            fma2(acc[0][2], p0, b2); fma2(acc[0][3], p0, b3);                    \
            fma2(acc[1][0], p1, b0); fma2(acc[1][1], p1, b1);                    \
            fma2(acc[1][2], p1, b2); fma2(acc[1][3], p1, b3);                    \
            fma2(acc[2][0], p2, b0); fma2(acc[2][1], p2, b1);                    \
            fma2(acc[2][2], p2, b2); fma2(acc[2][3], p2, b3);                    \
            fma2(acc[3][0], p3, b0); fma2(acc[3][1], p3, b1);                    \
            fma2(acc[3][2], p3, b2); fma2(acc[3][3], p3, b3);                    \
        }                                                                        \
    }

#define GEMM_PROLOG()                                                            \
    int tid = threadIdx.x;                                                       \
    int m0 = blockIdx.x * 64;                                                    \
    int colbase = (tid & 31) << 2;                                               \
    int rowb = (tid >> 5) << 3;                                                  \
    u64 acc[4][4];                                                               \
    _Pragma("unroll")                                                            \
    for (int i = 0; i < 4; i++) { acc[i][0] = 0; acc[i][1] = 0; acc[i][2] = 0; acc[i][3] = 0; }

#define UNPACK_ROWS(VR)                                                          \
    float4 VR[8];                                                                \
    _Pragma("unroll")                                                            \
    for (int i = 0; i < 4; i++) {                                                \
        unpack2(acc[i][0], VR[2*i].x, VR[2*i+1].x);                              \
        unpack2(acc[i][1], VR[2*i].y, VR[2*i+1].y);                              \
        unpack2(acc[i][2], VR[2*i].z, VR[2*i+1].z);                              \
        unpack2(acc[i][3], VR[2*i].w, VR[2*i+1].w);                              \
    }

// ---------------- gemm1: hpre += aggef@WeWlin1 + x@Wself1 + biases; stats --
__global__ __launch_bounds__(256) void gemm1_k(const float* __restrict__ x,
                                               const float* __restrict__ Wself1) {
    __shared__ __align__(16) float sA[32][68];
    __shared__ __align__(16) float sB[32][128];
    __shared__ float sBe[RR * DD];
    __shared__ float sBias[DD];
    __shared__ float sRed[2][DD];
    GEMM_PROLOG()
    for (int i = tid; i < RR * DD; i += 256) sBe[i] = g_beWlin1[i];
    if (tid < DD) { sBias[tid] = g_bias1[tid]; sRed[0][tid] = 0.f; sRed[1][tid] = 0.f; }

    GEMM_SEG(g_aggef, RR * EDD, g_WeWlin1, (size_t)mrow * (RR * EDD), NN)
    GEMM_SEG(x, DD, Wself1, (size_t)mrow * DD, NN)

    UNPACK_ROWS(vr)
    float4 la = make_float4(0.f, 0.f, 0.f, 0.f);
    float4 lb = make_float4(0.f, 0.f, 0.f, 0.f);
#pragma unroll
    for (int j = 0; j < 8; j++) {
        int m = m0 + rowb + j;
        if (m < NN) {
            float4 v = vr[j];
            float4 sc = *(const float4*)&g_hpre[(size_t)m * DD + colbase];
            v.x += sc.x + sBias[colbase + 0];
            v.y += sc.y + sBias[colbase + 1];
            v.z += sc.z + sBias[colbase + 2];
            v.w += sc.w + sBias[colbase + 3];
#pragma unroll
            for (int r = 0; r < RR; r++) {
                if (g_deg[m * RR + r] > 0.f) {
                    v.x += sBe[r * DD + colbase + 0];
                    v.y += sBe[r * DD + colbase + 1];
                    v.z += sBe[r * DD + colbase + 2];
                    v.w += sBe[r * DD + colbase + 3];
                }
            }
            *(float4*)&g_hpre[(size_t)m * DD + colbase] = v;
            la.x += v.x; la.y += v.y; la.z += v.z; la.w += v.w;
            lb.x += v.x * v.x; lb.y += v.y * v.y; lb.z += v.z * v.z; lb.w += v.w * v.w;
        }
    }
    atomicAdd(&sRed[0][colbase + 0], la.x); atomicAdd(&sRed[0][colbase + 1], la.y);
    atomicAdd(&sRed[0][colbase + 2], la.z); atomicAdd(&sRed[0][colbase + 3], la.w);
    atomicAdd(&sRed[1][colbase + 0], lb.x); atomicAdd(&sRed[1][colbase + 1], lb.y);
    atomicAdd(&sRed[1][colbase + 2], lb.z); atomicAdd(&sRed[1][colbase + 3], lb.w);
    __syncthreads();
    if (tid < DD) {
        atomicAdd(&g_s1a[tid], (double)sRed[0][tid]);
        atomicAdd(&g_s2a[tid], (double)sRed[1][tid]);
    }
}

// ---------------- h2: BN1+ReLU fused A-load; y=0: hW2=h@Wlin2, y=1: hs ----
__global__ __launch_bounds__(256) void h2_k(const float* __restrict__ Wlin2,
                                            const float* __restrict__ Wself2) {
    __shared__ __align__(16) float sA[32][68];
    __shared__ __align__(16) float sB[32][128];
    __shared__ float sBias[DD];
    __shared__ float sSc[DD], sSh[DD];
    int ysel = blockIdx.y;
    GEMM_PROLOG()
    if (tid < DD) { sBias[tid] = g_bias2[tid]; sSc[tid] = g_sc1[tid]; sSh[tid] = g_sh1[tid]; }
    const float* B = ysel ? Wself2 : Wlin2;
    GEMM_SEG_BN(g_hpre, DD, B, (size_t)mrow * DD, NN)
    UNPACK_ROWS(vr)
    float* dst = ysel ? g_hs : g_hW2;
#pragma unroll
    for (int j = 0; j < 8; j++) {
        int m = m0 + rowb + j;
        if (m < NN) {
            float4 v = vr[j];
            if (ysel) {
                v.x += sBias[colbase + 0]; v.y += sBias[colbase + 1];
                v.z += sBias[colbase + 2]; v.w += sBias[colbase + 3];
            }
            *(float4*)&dst[(size_t)m * DD + colbase] = v;
        }
    }
}

// ---------------- ef2init: out = aggef@WeWlin2 + hs + mask*beWlin2 --------
__global__ __launch_bounds__(256) void ef2init_k(float* __restrict__ out) {
    __shared__ __align__(16) float sA[32][68];
    __shared__ __align__(16) float sB[32][128];
    __shared__ float sBe2[DD];
    GEMM_PROLOG()
    if (tid < DD) sBe2[tid] = g_beWlin2[tid];

    GEMM_SEG(g_aggef, EDD, g_WeWlin2,
             (size_t)((mrow % NN) * RR + (mrow / NN)) * EDD, M2)

    UNPACK_ROWS(vr)
#pragma unroll
    for (int j = 0; j < 8; j++) {
        int m = m0 + rowb + j;
        int r = m / NN;
        int n = m - r * NN;
        float4 v = vr[j];
        float4 hsv = *(const float4*)&g_hs[(size_t)n * DD + colbase];
        v.x += hsv.x; v.y += hsv.y; v.z += hsv.z; v.w += hsv.w;
        if (g_deg[n * RR + r] > 0.f) {
            v.x += sBe2[colbase + 0]; v.y += sBe2[colbase + 1];
            v.z += sBe2[colbase + 2]; v.w += sBe2[colbase + 3];
        }
        *(float4*)&out[(size_t)m * DD + colbase] = v;
    }
}

// ---------------- scatter layer 2: red directly into out [R,N,128] -------
__global__ __launch_bounds__(256) void scatter2_k(
    const int* __restrict__ nin, const int* __restrict__ nout,
    const int* __restrict__ rel, const float* __restrict__ w,
    float* __restrict__ out)
{
    int idx = blockIdx.x * 256 + threadIdx.x;
    int e = idx >> 5;
    int lane = idx & 31;
    if (e >= EE) return;
    int ni = __ldg(nin + e);
    int no = __ldg(nout + e);
    int r  = __ldg(rel + e);
    int nor = no * RR + r;
    float ew = __ldg(w + e) / g_deg[nor];

    float4 hv = *(const float4*)&g_hW2[(size_t)ni * DD + lane * 4];
    hv.x *= ew; hv.y *= ew; hv.z *= ew; hv.w *= ew;
    red_add_v4(&out[((size_t)r * NN + no) * DD + lane * 4], hv);
}

// ---------------- stats over out ----------------
__global__ __launch_bounds__(128) void stats2_k(const float* __restrict__ out) {
    int d = threadIdx.x;
    int r0 = blockIdx.x * 256;
    int rend = r0 + 256;
    if (rend > M2) rend = M2;
    float a = 0.f, b = 0.f;
    for (int r = r0; r < rend; r++) {
        float v = out[(size_t)r * DD + d];
        a += v;
        b += v * v;
    }
    atomicAdd(&g_s1b[d], (double)a);
    atomicAdd(&g_s2b[d], (double)b);
}

// ---------------- BN finalize / apply ----------------
__global__ void bnfin_k(int sel, float nrows, const float* __restrict__ g,
                        const float* __restrict__ b) {
    int d = threadIdx.x;
    double s1 = sel ? g_s1b[d] : g_s1a[d];
    double s2 = sel ? g_s2b[d] : g_s2a[d];
    double m = s1 / (double)nrows;
    double var = s2 / (double)nrows - m * m;
    float sc = g[d] * rsqrtf((float)var + 1e-5f);
    float sh = b[d] - (float)m * sc;
    if (sel) { g_sc2[d] = sc; g_sh2[d] = sh; }
    else     { g_sc1[d] = sc; g_sh1[d] = sh; }
}

__global__ __launch_bounds__(256) void bnrelu_o_k(float* __restrict__ out) {
    int i = blockIdx.x * 256 + threadIdx.x;
    if (i >= M2 * 32) return;
    int c = (i & 31) << 2;
    float4 v = ((const float4*)out)[i];
    v.x = fmaxf(0.f, v.x * g_sc2[c + 0] + g_sh2[c + 0]);
    v.y = fmaxf(0.f, v.y * g_sc2[c + 1] + g_sh2[c + 1]);
    v.z = fmaxf(0.f, v.z * g_sc2[c + 2] + g_sh2[c + 2]);
    v.w = fmaxf(0.f, v.w * g_sc2[c + 3] + g_sh2[c + 3]);
    ((float4*)out)[i] = v;
}

// ---------------- launch ----------------
extern "C" void kernel_launch(void* const* d_in, const int* in_sizes, int n_in,
                              void* d_out, int out_size) {
    (void)in_sizes; (void)n_in; (void)out_size;
    const float* x        = (const float*)d_in[0];
    const int*   node_in  = (const int*)d_in[1];
    const int*   node_out = (const int*)d_in[2];
    const int*   relation = (const int*)d_in[3];
    const float* ew       = (const float*)d_in[4];
    const float* ef       = (const float*)d_in[5];
    const float* l1_Wlin  = (const float*)d_in[6];
    const float* l1_blin  = (const float*)d_in[7];
    const float* l1_Wself = (const float*)d_in[8];
    const float* l1_bself = (const float*)d_in[9];
    const float* l1_Wedge = (const float*)d_in[10];
    const float* l1_bedge = (const float*)d_in[11];
    const float* l1_g     = (const float*)d_in[12];
    const float* l1_b     = (const float*)d_in[13];
    const float* l2_Wlin  = (const float*)d_in[14];
    const float* l2_blin  = (const float*)d_in[15];
    const float* l2_Wself = (const float*)d_in[16];
    const float* l2_bself = (const float*)d_in[17];
    const float* l2_Wedge = (const float*)d_in[18];
    const float* l2_bedge = (const float*)d_in[19];
    const float* l2_g     = (const float*)d_in[20];
    const float* l2_b     = (const float*)d_in[21];
    float* out = (float*)d_out;

    int gm1 = (NN + 63) / 64;   // 782

    static int configured = 0;
    if (!configured) {
        cudaFuncSetAttribute(xw_mma_k, cudaFuncAttributeMaxDynamicSharedMemorySize,
                             XW_SMEM_BYTES);
        configured = 1;
    }

    zero_k<<<2048, 256>>>();
    prep_k<<<RR + 1, 128>>>(l1_Wedge, l1_Wlin, l1_bedge, l1_blin, l1_bself,
                            l2_Wedge, l2_Wlin, l2_bedge, l2_blin, l2_bself);
    deg_k<<<EE / 256, 256>>>(node_out, relation, ew);
    xw_mma_k<<<dim3((NN + 127) / 128, RR), 256, XW_SMEM_BYTES>>>(x, l1_Wlin);
    scatter1_k<<<EE / 8, 256>>>(node_in, node_out, relation, ew, ef);
    gemm1_k<<<gm1, 256>>>(x, l1_Wself);
    bnfin_k<<<1, 128>>>(0, (float)NN, l1_g, l1_b);
    h2_k<<<dim3(gm1, 2), 256>>>(l2_Wlin, l2_Wself);
    ef2init_k<<<M2 / 64, 256>>>(out);
    scatter2_k<<<EE / 8, 256>>>(node_in, node_out, relation, ew, out);
    stats2_k<<<(M2 + 255) / 256, 128>>>(out);
    bnfin_k<<<1, 128>>>(1, (float)M2, l2_g, l2_b);
    bnrelu_o_k<<<(M2 * 32) / 256, 256>>>(out);
}

// round 5
// speedup vs baseline: 1.8428x; 1.1141x over previous
#include <cuda_runtime.h>
#include <cstdint>

#define NN 50000
#define DD 128
#define RR 8
#define EE 800000
#define EDD 32
#define NR (NN*RR)
#define M2 (RR*NN)

typedef unsigned long long u64;

// ---------------- scratch ----------------
__device__ float g_deg[NR];
__device__ float g_aggef[NR*EDD];
__device__ float g_xW[(size_t)NN*RR*DD];  // [n, r, 128]
__device__ float g_hpre[NN*DD];
__device__ float g_h[NN*DD];
__device__ float g_hW2[NN*DD];
__device__ float g_hs[NN*DD];
__device__ float g_WeWlin1[RR*EDD*DD];
__device__ float g_WeWlin2[EDD*DD];
__device__ float g_beWlin1[RR*DD];
__device__ float g_beWlin2[DD];
__device__ float g_bias1[DD];
__device__ float g_bias2[DD];
__device__ double g_s1a[DD], g_s2a[DD], g_s1b[DD], g_s2b[DD];
__device__ float g_sc1[DD], g_sh1[DD], g_sc2[DD], g_sh2[DD];

// ---------------- helpers ----------------
__device__ __forceinline__ uint32_t smem_u32(const void* p) {
    uint32_t a;
    asm("{ .reg .u64 t; cvta.to.shared.u64 t, %1; cvt.u32.u64 %0, t; }" : "=r"(a) : "l"(p));
    return a;
}
__device__ __forceinline__ u64 pack2(float lo, float hi) {
    u64 r; asm("mov.b64 %0, {%1, %2};" : "=l"(r) : "f"(lo), "f"(hi)); return r;
}
__device__ __forceinline__ u64 dup2(float v) {
    u64 r; asm("mov.b64 %0, {%1, %1};" : "=l"(r) : "f"(v)); return r;
}
__device__ __forceinline__ void unpack2(u64 v, float& lo, float& hi) {
    asm("mov.b64 {%0, %1}, %2;" : "=f"(lo), "=f"(hi) : "l"(v));
}
__device__ __forceinline__ void fma2(u64& d, u64 a, u64 b) {
    asm("fma.rn.f32x2 %0, %1, %2, %0;" : "+l"(d) : "l"(a), "l"(b));
}
__device__ __forceinline__ void red_add_v4(float* p, float4 v) {
    asm volatile("red.global.add.v4.f32 [%0], {%1, %2, %3, %4};"
                 :: "l"(p), "f"(v.x), "f"(v.y), "f"(v.z), "f"(v.w) : "memory");
}
__device__ __forceinline__ void mma_tf32(float* d, const uint32_t* a,
                                         uint32_t b0, uint32_t b1) {
    asm volatile(
        "mma.sync.aligned.m16n8k8.row.col.f32.tf32.tf32.f32 "
        "{%0,%1,%2,%3}, {%4,%5,%6,%7}, {%8,%9}, {%0,%1,%2,%3};"
        : "+f"(d[0]), "+f"(d[1]), "+f"(d[2]), "+f"(d[3])
        : "r"(a[0]), "r"(a[1]), "r"(a[2]), "r"(a[3]), "r"(b0), "r"(b1));
}
__device__ __forceinline__ void cpa16(uint32_t d, const float* s) {
    asm volatile("cp.async.ca.shared.global [%0], [%1], 16;" :: "r"(d), "l"(s) : "memory");
}

// ---------------- zero ----------------
__global__ void zero_k() {
    size_t i = (size_t)blockIdx.x * blockDim.x + threadIdx.x;
    size_t stride = (size_t)gridDim.x * blockDim.x;
    float4 z = make_float4(0.f, 0.f, 0.f, 0.f);
    float4* e = (float4*)g_aggef;
    for (size_t j = i; j < (size_t)NR * EDD / 4; j += stride) e[j] = z;
    float4* h = (float4*)g_hpre;
    for (size_t j = i; j < (size_t)NN * DD / 4; j += stride) h[j] = z;
    float4* d = (float4*)g_deg;
    for (size_t j = i; j < (size_t)NR / 4; j += stride) d[j] = z;
    if (i < DD) { g_s1a[i] = 0.0; g_s2a[i] = 0.0; g_s1b[i] = 0.0; g_s2b[i] = 0.0; }
}

// ---------------- prep: folds ----------------
__global__ __launch_bounds__(128) void prep_k(
    const float* __restrict__ l1_We, const float* __restrict__ l1_Wlin,
    const float* __restrict__ l1_be, const float* __restrict__ l1_blin,
    const float* __restrict__ l1_bself,
    const float* __restrict__ l2_We, const float* __restrict__ l2_Wlin,
    const float* __restrict__ l2_be, const float* __restrict__ l2_blin,
    const float* __restrict__ l2_bself)
{
    __shared__ float sWe[EDD * DD];
    __shared__ float sbe[DD];
    int r = blockIdx.x;
    int d = threadIdx.x;
    const float* We = (r < RR) ? l1_We : l2_We;
    const float* Wl = (r < RR) ? l1_Wlin : l2_Wlin;
    const float* be = (r < RR) ? l1_be : l2_be;
    for (int i = d; i < EDD * DD; i += 128) sWe[i] = We[i];
    sbe[d] = be[d];
    __syncthreads();
    float acc[EDD];
#pragma unroll
    for (int i = 0; i < EDD; i++) acc[i] = 0.f;
    float accb = 0.f;
    int rowoff = (r < RR) ? r * DD : 0;
    for (int k = 0; k < DD; k++) {
        float wl = Wl[(size_t)(rowoff + k) * DD + d];
        accb += sbe[k] * wl;
#pragma unroll
        for (int i = 0; i < EDD; i++) acc[i] += sWe[i * DD + k] * wl;
    }
    if (r < RR) {
#pragma unroll
        for (int i = 0; i < EDD; i++) g_WeWlin1[(size_t)(r * EDD + i) * DD + d] = acc[i];
        g_beWlin1[r * DD + d] = accb;
    } else {
#pragma unroll
        for (int i = 0; i < EDD; i++) g_WeWlin2[(size_t)i * DD + d] = acc[i];
        g_beWlin2[d] = accb;
        g_bias1[d] = l1_blin[d] + l1_bself[d];
        g_bias2[d] = l2_blin[d] + l2_bself[d];
    }
}

// ---------------- degree ----------------
__global__ void deg_k(const int* __restrict__ nout, const int* __restrict__ rel,
                      const float* __restrict__ w) {
    int e = blockIdx.x * blockDim.x + threadIdx.x;
    if (e < EE) atomicAdd(&g_deg[nout[e] * RR + rel[e]], w[e]);
}

// ---------------- pipelined tf32 MMA: C[128x128] = A[128x128] @ B[128x128] --
// mode 0: A=x, B=Wlin1_r (r=blockIdx.y), dst=g_xW[:, r*128:...], stride RR*DD
// mode 1: A=g_h; y=0: B=Wlin2 -> g_hW2 ; y=1: B=Wself2 -> g_hs (+bias2)
#define A_FLOATS (128*36)                    /* 4608 */
#define B_FLOATS (32*132)                    /* 4224 */
#define STG_FLOATS (A_FLOATS + B_FLOATS)     /* 8832 */
#define MMA_SMEM (3 * STG_FLOATS * 4)        /* 105984 */

__global__ void __launch_bounds__(256, 2) mma_k(
    const float* __restrict__ Aext,
    const float* __restrict__ B0, const float* __restrict__ B1, int mode)
{
    extern __shared__ float smf[];
    int tid = threadIdx.x;
    int m0 = blockIdx.x * 128;
    int rsel = blockIdx.y;

    const float* A = (mode == 0) ? Aext : g_h;
    const float* B;
    float* dst;
    size_t rstride;
    int coff;
    const float* bias = nullptr;
    if (mode == 0) {
        B = B0 + (size_t)rsel * DD * DD;
        dst = g_xW; rstride = RR * DD; coff = rsel * DD;
    } else {
        if (rsel == 0) { B = B0; dst = g_hW2; }
        else           { B = B1; dst = g_hs; bias = g_bias2; }
        rstride = DD; coff = 0;
    }

    uint32_t sb = smem_u32(smf);

    auto load_stage = [&](int s, int k0) {
        float4 z = make_float4(0.f, 0.f, 0.f, 0.f);
#pragma unroll
        for (int j = 0; j < 4; j++) {
            int p = tid + j * 256;
            int row = p >> 3;
            int kq = (p & 7) << 2;
            int idx = s * STG_FLOATS + row * 36 + kq;
            int m = m0 + row;
            if (m < NN) cpa16(sb + idx * 4, A + (size_t)m * DD + k0 + kq);
            else *(float4*)&smf[idx] = z;
        }
#pragma unroll
        for (int j = 0; j < 4; j++) {
            int p = tid + j * 256;
            int k = p >> 5;
            int n4 = (p & 31) << 2;
            int idx = s * STG_FLOATS + A_FLOATS + k * 132 + n4;
            cpa16(sb + idx * 4, B + (size_t)(k0 + k) * DD + n4);
        }
        asm volatile("cp.async.commit_group;" ::: "memory");
    };

    int wid = tid >> 5, lane = tid & 31;
    int g = lane >> 2, t = lane & 3;
    int wm = (wid & 3) * 32, wn = (wid >> 2) * 64;

    float acc[2][8][4];
#pragma unroll
    for (int mi = 0; mi < 2; mi++)
#pragma unroll
        for (int ni = 0; ni < 8; ni++) {
            acc[mi][ni][0] = 0.f; acc[mi][ni][1] = 0.f;
            acc[mi][ni][2] = 0.f; acc[mi][ni][3] = 0.f;
        }

    load_stage(0, 0);
    load_stage(1, 32);

#pragma unroll
    for (int kc = 0; kc < 4; kc++) {
        if (kc + 2 < 4) load_stage((kc + 2) % 3, (kc + 2) * 32);
        if (kc <= 1)      asm volatile("cp.async.wait_group 2;" ::: "memory");
        else if (kc == 2) asm volatile("cp.async.wait_group 1;" ::: "memory");
        else              asm volatile("cp.async.wait_group 0;" ::: "memory");
        __syncthreads();
        const float* cA = smf + (kc % 3) * STG_FLOATS;
        const float* cB = cA + A_FLOATS;
#pragma unroll
        for (int ks = 0; ks < 4; ks++) {
            int kb = ks * 8;
            uint32_t a[2][4];
#pragma unroll
            for (int mi = 0; mi < 2; mi++) {
                int bm = wm + mi * 16;
                a[mi][0] = __float_as_uint(cA[(bm + g) * 36 + kb + t]);
                a[mi][1] = __float_as_uint(cA[(bm + g + 8) * 36 + kb + t]);
                a[mi][2] = __float_as_uint(cA[(bm + g) * 36 + kb + t + 4]);
                a[mi][3] = __float_as_uint(cA[(bm + g + 8) * 36 + kb + t + 4]);
            }
#pragma unroll
            for (int ni = 0; ni < 8; ni++) {
                int bn = wn + ni * 8;
                uint32_t b0 = __float_as_uint(cB[(kb + t) * 132 + bn + g]);
                uint32_t b1 = __float_as_uint(cB[(kb + t + 4) * 132 + bn + g]);
                mma_tf32(acc[0][ni], a[0], b0, b1);
                mma_tf32(acc[1][ni], a[1], b0, b1);
            }
        }
        __syncthreads();
    }

#pragma unroll
    for (int mi = 0; mi < 2; mi++) {
#pragma unroll
        for (int ni = 0; ni < 8; ni++) {
            int mg = m0 + wm + mi * 16 + g;
            int c = wn + ni * 8 + 2 * t;
            float2 v0 = make_float2(acc[mi][ni][0], acc[mi][ni][1]);
            float2 v1 = make_float2(acc[mi][ni][2], acc[mi][ni][3]);
            if (bias) {
                float b0 = bias[c], b1 = bias[c + 1];
                v0.x += b0; v0.y += b1; v1.x += b0; v1.y += b1;
            }
            if (mg < NN) *(float2*)&dst[(size_t)mg * rstride + coff + c] = v0;
            if (mg + 8 < NN) *(float2*)&dst[(size_t)(mg + 8) * rstride + coff + c] = v1;
        }
    }
}

// ---------------- scatter layer 1 ----------------
__global__ __launch_bounds__(256) void scatter1_k(
    const int* __restrict__ nin, const int* __restrict__ nout,
    const int* __restrict__ rel, const float* __restrict__ w,
    const float* __restrict__ ef)
{
    int idx = blockIdx.x * 256 + threadIdx.x;
    int e = idx >> 5;
    int lane = idx & 31;
    if (e >= EE) return;
    int ni = __ldg(nin + e);
    int no = __ldg(nout + e);
    int r  = __ldg(rel + e);
    int nor = no * RR + r;
    float ew = __ldg(w + e) / g_deg[nor];

    float4 xv = *(const float4*)&g_xW[(size_t)ni * (RR * DD) + r * DD + lane * 4];
    xv.x *= ew; xv.y *= ew; xv.z *= ew; xv.w *= ew;
    red_add_v4(&g_hpre[(size_t)no * DD + lane * 4], xv);

    if (lane < 8) {
        float4 ev = *(const float4*)&ef[(size_t)e * EDD + lane * 4];
        ev.x *= ew; ev.y *= ew; ev.z *= ew; ev.w *= ew;
        red_add_v4(&g_aggef[(size_t)nor * EDD + lane * 4], ev);
    }
}

// ---------------- GEMM tile macros (fp32, f32x2) ----------------
#define GEMM_SEG(APTR, KTOT, BPTR, ROWEXPR, MROWS)                               \
    for (int k0 = 0; k0 < (KTOT); k0 += 32) {                                    \
        __syncthreads();                                                         \
        {                                                                        \
            int arow = tid >> 3;                                                 \
            int fc = (tid & 7) << 2;                                             \
            _Pragma("unroll")                                                    \
            for (int rr2 = 0; rr2 < 2; rr2++) {                                  \
                int mrow = m0 + arow + rr2 * 32;                                 \
                float4 av = make_float4(0.f, 0.f, 0.f, 0.f);                     \
                if (mrow < (MROWS)) {                                            \
                    size_t aoff = (ROWEXPR);                                     \
                    av = *(const float4*)((APTR) + aoff + k0 + fc);              \
                }                                                                \
                sA[fc + 0][arow + rr2 * 32] = av.x;                              \
                sA[fc + 1][arow + rr2 * 32] = av.y;                              \
                sA[fc + 2][arow + rr2 * 32] = av.z;                              \
                sA[fc + 3][arow + rr2 * 32] = av.w;                              \
            }                                                                    \
        }                                                                        \
        _Pragma("unroll")                                                        \
        for (int j = 0; j < 4; j++) {                                            \
            int bi = tid + j * 256;                                              \
            int kr = bi >> 5;                                                    \
            int c = (bi & 31) << 2;                                              \
            *(float4*)&sB[kr][c] = *(const float4*)((BPTR) + (size_t)(k0 + kr) * DD + c); \
        }                                                                        \
        __syncthreads();                                                         \
        _Pragma("unroll")                                                        \
        for (int kk = 0; kk < 32; kk++) {                                        \
            float4 bv = *(float4*)&sB[kk][colbase];                              \
            u64 b0 = dup2(bv.x), b1 = dup2(bv.y), b2 = dup2(bv.z), b3 = dup2(bv.w); \
            float4 a0 = *(float4*)&sA[kk][rowb];                                 \
            float4 a1 = *(float4*)&sA[kk][rowb + 4];                             \
            u64 p0 = pack2(a0.x, a0.y), p1 = pack2(a0.z, a0.w);                  \
            u64 p2 = pack2(a1.x, a1.y), p3 = pack2(a1.z, a1.w);                  \
            fma2(acc[0][0], p0, b0); fma2(acc[0][1], p0, b1);                    \
            fma2(acc[0][2], p0, b2); fma2(acc[0][3], p0, b3);                    \
            fma2(acc[1][0], p1, b0); fma2(acc[1][1], p1, b1);                    \
            fma2(acc[1][2], p1, b2); fma2(acc[1][3], p1, b3);                    \
            fma2(acc[2][0], p2, b0); fma2(acc[2][1], p2, b1);                    \
            fma2(acc[2][2], p2, b2); fma2(acc[2][3], p2, b3);                    \
            fma2(acc[3][0], p3, b0); fma2(acc[3][1], p3, b1);                    \
            fma2(acc[3][2], p3, b2); fma2(acc[3][3], p3, b3);                    \
        }                                                                        \
    }

#define GEMM_PROLOG()                                                            \
    int tid = threadIdx.x;                                                       \
    int m0 = blockIdx.x * 64;                                                    \
    int colbase = (tid & 31) << 2;                                               \
    int rowb = (tid >> 5) << 3;                                                  \
    u64 acc[4][4];                                                               \
    _Pragma("unroll")                                                            \
    for (int i = 0; i < 4; i++) { acc[i][0] = 0; acc[i][1] = 0; acc[i][2] = 0; acc[i][3] = 0; }

#define UNPACK_ROWS(VR)                                                          \
    float4 VR[8];                                                                \
    _Pragma("unroll")                                                            \
    for (int i = 0; i < 4; i++) {                                                \
        unpack2(acc[i][0], VR[2*i].x, VR[2*i+1].x);                              \
        unpack2(acc[i][1], VR[2*i].y, VR[2*i+1].y);                              \
        unpack2(acc[i][2], VR[2*i].z, VR[2*i+1].z);                              \
        unpack2(acc[i][3], VR[2*i].w, VR[2*i+1].w);                              \
    }

// ---------------- gemm1: hpre += aggef@WeWlin1 + x@Wself1 + biases; stats --
__global__ __launch_bounds__(256) void gemm1_k(const float* __restrict__ x,
                                               const float* __restrict__ Wself1) {
    __shared__ __align__(16) float sA[32][68];
    __shared__ __align__(16) float sB[32][128];
    __shared__ float sBe[RR * DD];
    __shared__ float sBias[DD];
    __shared__ float sRed[2][DD];
    GEMM_PROLOG()
    for (int i = tid; i < RR * DD; i += 256) sBe[i] = g_beWlin1[i];
    if (tid < DD) { sBias[tid] = g_bias1[tid]; sRed[0][tid] = 0.f; sRed[1][tid] = 0.f; }

    GEMM_SEG(g_aggef, RR * EDD, g_WeWlin1, (size_t)mrow * (RR * EDD), NN)
    GEMM_SEG(x, DD, Wself1, (size_t)mrow * DD, NN)

    UNPACK_ROWS(vr)
    float4 la = make_float4(0.f, 0.f, 0.f, 0.f);
    float4 lb = make_float4(0.f, 0.f, 0.f, 0.f);
#pragma unroll
    for (int j = 0; j < 8; j++) {
        int m = m0 + rowb + j;
        if (m < NN) {
            float4 v = vr[j];
            float4 sc = *(const float4*)&g_hpre[(size_t)m * DD + colbase];
            v.x += sc.x + sBias[colbase + 0];
            v.y += sc.y + sBias[colbase + 1];
            v.z += sc.z + sBias[colbase + 2];
            v.w += sc.w + sBias[colbase + 3];
#pragma unroll
            for (int r = 0; r < RR; r++) {
                if (g_deg[m * RR + r] > 0.f) {
                    v.x += sBe[r * DD + colbase + 0];
                    v.y += sBe[r * DD + colbase + 1];
                    v.z += sBe[r * DD + colbase + 2];
                    v.w += sBe[r * DD + colbase + 3];
                }
            }
            *(float4*)&g_hpre[(size_t)m * DD + colbase] = v;
            la.x += v.x; la.y += v.y; la.z += v.z; la.w += v.w;
            lb.x += v.x * v.x; lb.y += v.y * v.y; lb.z += v.z * v.z; lb.w += v.w * v.w;
        }
    }
    atomicAdd(&sRed[0][colbase + 0], la.x); atomicAdd(&sRed[0][colbase + 1], la.y);
    atomicAdd(&sRed[0][colbase + 2], la.z); atomicAdd(&sRed[0][colbase + 3], la.w);
    atomicAdd(&sRed[1][colbase + 0], lb.x); atomicAdd(&sRed[1][colbase + 1], lb.y);
    atomicAdd(&sRed[1][colbase + 2], lb.z); atomicAdd(&sRed[1][colbase + 3], lb.w);
    __syncthreads();
    if (tid < DD) {
        atomicAdd(&g_s1a[tid], (double)sRed[0][tid]);
        atomicAdd(&g_s2a[tid], (double)sRed[1][tid]);
    }
}

// ---------------- ef2init: out = aggef@WeWlin2 + hs + mask*beWlin2 --------
__global__ __launch_bounds__(256) void ef2init_k(float* __restrict__ out) {
    __shared__ __align__(16) float sA[32][68];
    __shared__ __align__(16) float sB[32][128];
    __shared__ float sBe2[DD];
    GEMM_PROLOG()
    if (tid < DD) sBe2[tid] = g_beWlin2[tid];

    GEMM_SEG(g_aggef, EDD, g_WeWlin2,
             (size_t)((mrow % NN) * RR + (mrow / NN)) * EDD, M2)

    UNPACK_ROWS(vr)
#pragma unroll
    for (int j = 0; j < 8; j++) {
        int m = m0 + rowb + j;
        int r = m / NN;
        int n = m - r * NN;
        float4 v = vr[j];
        float4 hsv = *(const float4*)&g_hs[(size_t)n * DD + colbase];
        v.x += hsv.x; v.y += hsv.y; v.z += hsv.z; v.w += hsv.w;
        if (g_deg[n * RR + r] > 0.f) {
            v.x += sBe2[colbase + 0]; v.y += sBe2[colbase + 1];
            v.z += sBe2[colbase + 2]; v.w += sBe2[colbase + 3];
        }
        *(float4*)&out[(size_t)m * DD + colbase] = v;
    }
}

// ---------------- scatter layer 2 ----------------
__global__ __launch_bounds__(256) void scatter2_k(
    const int* __restrict__ nin, const int* __restrict__ nout,
    const int* __restrict__ rel, const float* __restrict__ w,
    float* __restrict__ out)
{
    int idx = blockIdx.x * 256 + threadIdx.x;
    int e = idx >> 5;
    int lane = idx & 31;
    if (e >= EE) return;
    int ni = __ldg(nin + e);
    int no = __ldg(nout + e);
    int r  = __ldg(rel + e);
    int nor = no * RR + r;
    float ew = __ldg(w + e) / g_deg[nor];

    float4 hv = *(const float4*)&g_hW2[(size_t)ni * DD + lane * 4];
    hv.x *= ew; hv.y *= ew; hv.z *= ew; hv.w *= ew;
    red_add_v4(&out[((size_t)r * NN + no) * DD + lane * 4], hv);
}

// ---------------- stats over out ----------------
__global__ __launch_bounds__(128) void stats2_k(const float* __restrict__ out) {
    int d = threadIdx.x;
    int r0 = blockIdx.x * 256;
    int rend = r0 + 256;
    if (rend > M2) rend = M2;
    float a = 0.f, b = 0.f;
    for (int r = r0; r < rend; r++) {
        float v = out[(size_t)r * DD + d];
        a += v;
        b += v * v;
    }
    atomicAdd(&g_s1b[d], (double)a);
    atomicAdd(&g_s2b[d], (double)b);
}

// ---------------- BN finalize / apply ----------------
__global__ void bnfin_k(int sel, float nrows, const float* __restrict__ g,
                        const float* __restrict__ b) {
    int d = threadIdx.x;
    double s1 = sel ? g_s1b[d] : g_s1a[d];
    double s2 = sel ? g_s2b[d] : g_s2a[d];
    double m = s1 / (double)nrows;
    double var = s2 / (double)nrows - m * m;
    float sc = g[d] * rsqrtf((float)var + 1e-5f);
    float sh = b[d] - (float)m * sc;
    if (sel) { g_sc2[d] = sc; g_sh2[d] = sh; }
    else     { g_sc1[d] = sc; g_sh1[d] = sh; }
}

__global__ __launch_bounds__(256) void bnrelu_h_k() {
    int i = blockIdx.x * 256 + threadIdx.x;
    if (i >= NN * 32) return;
    int c = (i & 31) << 2;
    float4 v = ((const float4*)g_hpre)[i];
    v.x = fmaxf(0.f, v.x * g_sc1[c + 0] + g_sh1[c + 0]);
    v.y = fmaxf(0.f, v.y * g_sc1[c + 1] + g_sh1[c + 1]);
    v.z = fmaxf(0.f, v.z * g_sc1[c + 2] + g_sh1[c + 2]);
    v.w = fmaxf(0.f, v.w * g_sc1[c + 3] + g_sh1[c + 3]);
    ((float4*)g_h)[i] = v;
}

__global__ __launch_bounds__(256) void bnrelu_o_k(float* __restrict__ out) {
    int i = blockIdx.x * 256 + threadIdx.x;
    if (i >= M2 * 32) return;
    int c = (i & 31) << 2;
    float4 v = ((const float4*)out)[i];
    v.x = fmaxf(0.f, v.x * g_sc2[c + 0] + g_sh2[c + 0]);
    v.y = fmaxf(0.f, v.y * g_sc2[c + 1] + g_sh2[c + 1]);
    v.z = fmaxf(0.f, v.z * g_sc2[c + 2] + g_sh2[c + 2]);
    v.w = fmaxf(0.f, v.w * g_sc2[c + 3] + g_sh2[c + 3]);
    ((float4*)out)[i] = v;
}

// ---------------- launch ----------------
extern "C" void kernel_launch(void* const* d_in, const int* in_sizes, int n_in,
                              void* d_out, int out_size) {
    (void)in_sizes; (void)n_in; (void)out_size;
    const float* x        = (const float*)d_in[0];
    const int*   node_in  = (const int*)d_in[1];
    const int*   node_out = (const int*)d_in[2];
    const int*   relation = (const int*)d_in[3];
    const float* ew       = (const float*)d_in[4];
    const float* ef       = (const float*)d_in[5];
    const float* l1_Wlin  = (const float*)d_in[6];
    const float* l1_blin  = (const float*)d_in[7];
    const float* l1_Wself = (const float*)d_in[8];
    const float* l1_bself = (const float*)d_in[9];
    const float* l1_Wedge = (const float*)d_in[10];
    const float* l1_bedge = (const float*)d_in[11];
    const float* l1_g     = (const float*)d_in[12];
    const float* l1_b     = (const float*)d_in[13];
    const float* l2_Wlin  = (const float*)d_in[14];
    const float* l2_blin  = (const float*)d_in[15];
    const float* l2_Wself = (const float*)d_in[16];
    const float* l2_bself = (const float*)d_in[17];
    const float* l2_Wedge = (const float*)d_in[18];
    const float* l2_bedge = (const float*)d_in[19];
    const float* l2_g     = (const float*)d_in[20];
    const float* l2_b     = (const float*)d_in[21];
    float* out = (float*)d_out;

    int gm1 = (NN + 63) / 64;     // 782
    int gmm = (NN + 127) / 128;   // 391

    static int configured = 0;
    if (!configured) {
        cudaFuncSetAttribute(mma_k, cudaFuncAttributeMaxDynamicSharedMemorySize,
                             MMA_SMEM);
        configured = 1;
    }

    zero_k<<<2048, 256>>>();
    prep_k<<<RR + 1, 128>>>(l1_Wedge, l1_Wlin, l1_bedge, l1_blin, l1_bself,
                            l2_Wedge, l2_Wlin, l2_bedge, l2_blin, l2_bself);
    deg_k<<<EE / 256, 256>>>(node_out, relation, ew);
    mma_k<<<dim3(gmm, RR), 256, MMA_SMEM>>>(x, l1_Wlin, nullptr, 0);
    scatter1_k<<<EE / 8, 256>>>(node_in, node_out, relation, ew, ef);
    gemm1_k<<<gm1, 256>>>(x, l1_Wself);
    bnfin_k<<<1, 128>>>(0, (float)NN, l1_g, l1_b);
    bnrelu_h_k<<<(NN * 32 + 255) / 256, 256>>>();
    mma_k<<<dim3(gmm, 2), 256, MMA_SMEM>>>(nullptr, l2_Wlin, l2_Wself, 1);
    ef2init_k<<<M2 / 64, 256>>>(out);
    scatter2_k<<<EE / 8, 256>>>(node_in, node_out, relation, ew, out);
    stats2_k<<<(M2 + 255) / 256, 128>>>(out);
    bnfin_k<<<1, 128>>>(1, (float)M2, l2_g, l2_b);
    bnrelu_o_k<<<(M2 * 32) / 256, 256>>>(out);
}